// round 1
// baseline (speedup 1.0000x reference)
#include <cuda_runtime.h>
#include <math.h>
#include <stdint.h>

// Problem constants
#define D_MODEL   1024
#define N_HEADS   16
#define HEAD_DIM  64
#define BATCH     2
#define SEQ       2048
#define M_ROWS    (BATCH * SEQ)            // 4096
#define OUT_ELEMS ((size_t)BATCH * SEQ * D_MODEL)  // 4,194,304
#define SCALE_F   0.125f                   // 64^-0.5

// Attention tiling
#define QT 16     // query rows per block
#define KT 128    // key tile

// Scratch (device globals; no allocation allowed)
__device__ float g_Q[BATCH * N_HEADS * SEQ * HEAD_DIM];
__device__ float g_K[BATCH * N_HEADS * SEQ * HEAD_DIM];
__device__ float g_V[BATCH * N_HEADS * SEQ * HEAD_DIM];
__device__ float g_ctx[BATCH * SEQ * D_MODEL];

// ---------------------------------------------------------------------------
// GEMM: C[M][D_MODEL] = X[M][D_MODEL] @ W[D_MODEL][D_MODEL]^T + bias
// (torch Linear). BM=BN=64, BK=16, 256 threads, 4x4 register tile.
// head_split=1: write to [B, H, S, Dh] layout. head_split=0: row-major [M, D].
// ---------------------------------------------------------------------------
__global__ void gemm_xwt(const float* __restrict__ X,
                         const float* __restrict__ W,
                         const float* __restrict__ bias,
                         float* __restrict__ outp,
                         int head_split)
{
    __shared__ float Xs[16][64];  // [k][m]
    __shared__ float Ws[16][64];  // [k][n]

    const int m0 = blockIdx.y * 64;
    const int n0 = blockIdx.x * 64;
    const int t  = threadIdx.x;

    const int lr = t >> 2;          // 0..63: tile row to load
    const int lc = (t & 3) * 4;     // 0,4,8,12: k-chunk
    const int tx = t & 15;          // 0..15
    const int ty = t >> 4;          // 0..15

    float acc[4][4] = {};

    for (int k0 = 0; k0 < D_MODEL; k0 += 16) {
        float4 xa = *(const float4*)&X[(size_t)(m0 + lr) * D_MODEL + k0 + lc];
        float4 wa = *(const float4*)&W[(size_t)(n0 + lr) * D_MODEL + k0 + lc];
        __syncthreads();
        Xs[lc + 0][lr] = xa.x; Xs[lc + 1][lr] = xa.y;
        Xs[lc + 2][lr] = xa.z; Xs[lc + 3][lr] = xa.w;
        Ws[lc + 0][lr] = wa.x; Ws[lc + 1][lr] = wa.y;
        Ws[lc + 2][lr] = wa.z; Ws[lc + 3][lr] = wa.w;
        __syncthreads();

        #pragma unroll
        for (int kk = 0; kk < 16; kk++) {
            float4 a = *(const float4*)&Xs[kk][ty * 4];
            float4 b = *(const float4*)&Ws[kk][tx * 4];
            acc[0][0] += a.x * b.x; acc[0][1] += a.x * b.y;
            acc[0][2] += a.x * b.z; acc[0][3] += a.x * b.w;
            acc[1][0] += a.y * b.x; acc[1][1] += a.y * b.y;
            acc[1][2] += a.y * b.z; acc[1][3] += a.y * b.w;
            acc[2][0] += a.z * b.x; acc[2][1] += a.z * b.y;
            acc[2][2] += a.z * b.z; acc[2][3] += a.z * b.w;
            acc[3][0] += a.w * b.x; acc[3][1] += a.w * b.y;
            acc[3][2] += a.w * b.z; acc[3][3] += a.w * b.w;
        }
    }

    #pragma unroll
    for (int i = 0; i < 4; i++) {
        const int m = m0 + ty * 4 + i;
        #pragma unroll
        for (int j = 0; j < 4; j++) {
            const int n = n0 + tx * 4 + j;
            const float v = acc[i][j] + bias[n];
            if (head_split) {
                const int b  = m >> 11;          // /SEQ
                const int s  = m & (SEQ - 1);
                const int hh = n >> 6;           // /HEAD_DIM
                const int dd = n & (HEAD_DIM - 1);
                outp[(((size_t)(b * N_HEADS + hh) * SEQ + s)) * HEAD_DIM + dd] = v;
            } else {
                outp[(size_t)m * D_MODEL + n] = v;
            }
        }
    }
}

// ---------------------------------------------------------------------------
// Fused attention per (b, h, q-tile of 16 rows):
//   scores (16x2048, in smem) -> softmax -> write attn (gmem) -> AV -> ctx
// ---------------------------------------------------------------------------
#define P_STRIDE   2052                  // 2048 + 4 (float4-aligned rows)
#define QST_STRIDE 17
#define KST_STRIDE 133                   // transposed K: conflict-free compute loads
#define VS_STRIDE  68                    // V tile: float4-aligned rows
// smem floats: P + QsT + max(KsT, Vs)
#define SM_P_F     (QT * P_STRIDE)                 // 32832
#define SM_Q_F     (HEAD_DIM * QST_STRIDE)         // 1088
#define SM_KV_F    (KT * VS_STRIDE)                // 8704 (>= 64*133 = 8512)
#define SMEM_FLOATS (SM_P_F + SM_Q_F + SM_KV_F)
#define SMEM_BYTES  (SMEM_FLOATS * 4)              // 170,496

__global__ void attn_kernel(float* __restrict__ out_all)
{
    const int qtile = blockIdx.x;    // 0..127
    const int h     = blockIdx.y;    // 0..15
    const int b     = blockIdx.z;    // 0..1
    const int q0    = qtile * QT;
    const int t     = threadIdx.x;   // 0..255

    extern __shared__ float sm[];
    float* P   = sm;                       // [QT][P_STRIDE]
    float* QsT = sm + SM_P_F;              // [64][17]  (transposed, pre-scaled)
    float* KVs = QsT + SM_Q_F;             // KsT [64][133] then Vs [128][68]

    const size_t headBase = (size_t)(b * N_HEADS + h) * SEQ * HEAD_DIM;
    const float* Qh = g_Q + headBase + (size_t)q0 * HEAD_DIM;
    const float* Kh = g_K + headBase;
    const float* Vh = g_V + headBase;

    // Load Q tile transposed, pre-scaled by 1/sqrt(Dh)
    for (int i = t; i < QT * HEAD_DIM; i += 256) {
        const int qi = i >> 6, d = i & 63;
        QsT[d * QST_STRIDE + qi] = Qh[(size_t)qi * HEAD_DIM + d] * SCALE_F;
    }

    const int tq = t >> 5;   // 0..7  -> query rows {tq, tq+8}
    const int tk = t & 31;   // 0..31 -> keys {tk + 32*j}

    // ---- Phase 1: scores into P ----
    for (int k0 = 0; k0 < SEQ; k0 += KT) {
        __syncthreads();
        // fill KsT[d][kl] (transposed), coalesced gmem read
        for (int i = t; i < KT * (HEAD_DIM / 4); i += 256) {
            const int kl = i >> 4;
            const int c4 = (i & 15) * 4;
            float4 kv = *(const float4*)&Kh[(size_t)(k0 + kl) * HEAD_DIM + c4];
            KVs[(c4 + 0) * KST_STRIDE + kl] = kv.x;
            KVs[(c4 + 1) * KST_STRIDE + kl] = kv.y;
            KVs[(c4 + 2) * KST_STRIDE + kl] = kv.z;
            KVs[(c4 + 3) * KST_STRIDE + kl] = kv.w;
        }
        __syncthreads();

        float acc0[4] = {}, acc1[4] = {};
        #pragma unroll 16
        for (int d = 0; d < HEAD_DIM; d++) {
            const float a0 = QsT[d * QST_STRIDE + tq];
            const float a1 = QsT[d * QST_STRIDE + tq + 8];
            const float* kr = &KVs[d * KST_STRIDE + tk];
            #pragma unroll
            for (int j = 0; j < 4; j++) {
                const float kb = kr[32 * j];
                acc0[j] += a0 * kb;
                acc1[j] += a1 * kb;
            }
        }
        #pragma unroll
        for (int j = 0; j < 4; j++) {
            P[tq * P_STRIDE + k0 + tk + 32 * j]       = acc0[j];
            P[(tq + 8) * P_STRIDE + k0 + tk + 32 * j] = acc1[j];
        }
    }
    __syncthreads();

    // ---- Phase 2: softmax rows, write attn to gmem, keep probs in P ----
    {
        const int warp = t >> 5, lane = t & 31;
        float* attn = out_all + OUT_ELEMS;
        const size_t attnBase = ((size_t)(b * N_HEADS + h) * SEQ + q0) * SEQ;
        for (int qi = warp; qi < QT; qi += 8) {
            float* row = P + qi * P_STRIDE;
            float mx = -1e30f;
            for (int k = lane; k < SEQ; k += 32) mx = fmaxf(mx, row[k]);
            #pragma unroll
            for (int off = 16; off; off >>= 1)
                mx = fmaxf(mx, __shfl_xor_sync(0xFFFFFFFFu, mx, off));

            float sum = 0.f;
            for (int k = lane * 4; k < SEQ; k += 128) {
                float4 s4 = *(float4*)&row[k];
                s4.x = __expf(s4.x - mx);
                s4.y = __expf(s4.y - mx);
                s4.z = __expf(s4.z - mx);
                s4.w = __expf(s4.w - mx);
                sum += s4.x + s4.y + s4.z + s4.w;
                *(float4*)&row[k] = s4;
            }
            #pragma unroll
            for (int off = 16; off; off >>= 1)
                sum += __shfl_xor_sync(0xFFFFFFFFu, sum, off);
            const float inv = 1.f / sum;

            float* arow = attn + attnBase + (size_t)qi * SEQ;
            for (int k = lane * 4; k < SEQ; k += 128) {
                float4 s4 = *(float4*)&row[k];
                s4.x *= inv; s4.y *= inv; s4.z *= inv; s4.w *= inv;
                *(float4*)&row[k]  = s4;   // normalized probs for AV phase
                *(float4*)&arow[k] = s4;   // attn output
            }
        }
    }
    __syncthreads();

    // ---- Phase 3: out = P @ V -> ctx ----
    const int td = (t & 31) * 2;   // 2 d-columns per thread
    float o00 = 0.f, o01 = 0.f, o10 = 0.f, o11 = 0.f;
    for (int k0 = 0; k0 < SEQ; k0 += KT) {
        __syncthreads();
        // fill Vs[kl][d] row-major, padded
        for (int i = t; i < KT * (HEAD_DIM / 4); i += 256) {
            const int kl = i >> 4;
            const int c4 = (i & 15) * 4;
            float4 vv = *(const float4*)&Vh[(size_t)(k0 + kl) * HEAD_DIM + c4];
            *(float4*)&KVs[kl * VS_STRIDE + c4] = vv;
        }
        __syncthreads();

        const float* p0r = &P[tq * P_STRIDE + k0];
        const float* p1r = &P[(tq + 8) * P_STRIDE + k0];
        #pragma unroll 8
        for (int kk = 0; kk < KT; kk++) {
            const float p0 = p0r[kk];
            const float p1 = p1r[kk];
            const float2 vv = *(const float2*)&KVs[kk * VS_STRIDE + td];
            o00 += p0 * vv.x; o01 += p0 * vv.y;
            o10 += p1 * vv.x; o11 += p1 * vv.y;
        }
    }
    // write ctx in [B, S, H*Dh] layout
    {
        const int d = h * HEAD_DIM + td;
        const size_t r0 = (size_t)(b * SEQ + q0 + tq) * D_MODEL + d;
        const size_t r1 = (size_t)(b * SEQ + q0 + tq + 8) * D_MODEL + d;
        g_ctx[r0] = o00; g_ctx[r0 + 1] = o01;
        g_ctx[r1] = o10; g_ctx[r1 + 1] = o11;
    }
}

// ---------------------------------------------------------------------------
extern "C" void kernel_launch(void* const* d_in, const int* in_sizes, int n_in,
                              void* d_out, int out_size)
{
    const float* q  = (const float*)d_in[0];
    const float* k  = (const float*)d_in[1];
    const float* v  = (const float*)d_in[2];
    const float* Wq = (const float*)d_in[3];
    const float* bq = (const float*)d_in[4];
    const float* Wk = (const float*)d_in[5];
    const float* bk = (const float*)d_in[6];
    const float* Wv = (const float*)d_in[7];
    const float* bv = (const float*)d_in[8];
    const float* Wo = (const float*)d_in[9];
    const float* bo = (const float*)d_in[10];
    float* out = (float*)d_out;

    float *Qp, *Kp, *Vp, *Cp;
    cudaGetSymbolAddress((void**)&Qp, g_Q);
    cudaGetSymbolAddress((void**)&Kp, g_K);
    cudaGetSymbolAddress((void**)&Vp, g_V);
    cudaGetSymbolAddress((void**)&Cp, g_ctx);

    cudaFuncSetAttribute(attn_kernel,
                         cudaFuncAttributeMaxDynamicSharedMemorySize, SMEM_BYTES);

    dim3 ggrid(D_MODEL / 64, M_ROWS / 64);  // (16, 64)
    gemm_xwt<<<ggrid, 256>>>(q, Wq, bq, Qp, 1);
    gemm_xwt<<<ggrid, 256>>>(k, Wk, bk, Kp, 1);
    gemm_xwt<<<ggrid, 256>>>(v, Wv, bv, Vp, 1);

    attn_kernel<<<dim3(SEQ / QT, N_HEADS, BATCH), 256, SMEM_BYTES>>>(out);

    gemm_xwt<<<ggrid, 256>>>(Cp, Wo, bo, out, 0);
}

// round 2
// speedup vs baseline: 2.0841x; 2.0841x over previous
#include <cuda_runtime.h>
#include <math.h>
#include <stdint.h>

// Problem constants
#define D_MODEL   1024
#define N_HEADS   16
#define HEAD_DIM  64
#define BATCH     2
#define SEQ       2048
#define M_ROWS    (BATCH * SEQ)                    // 4096
#define OUT_ELEMS ((size_t)BATCH * SEQ * D_MODEL)  // 4,194,304
#define SCALE_F   0.125f                           // 64^-0.5

// Scratch (device globals; no allocation allowed)
__device__ float g_Q[BATCH * N_HEADS * SEQ * HEAD_DIM];
__device__ float g_K[BATCH * N_HEADS * SEQ * HEAD_DIM];
__device__ float g_V[BATCH * N_HEADS * SEQ * HEAD_DIM];
__device__ float g_ctx[BATCH * SEQ * D_MODEL];

// ---------------------------------------------------------------------------
// tf32 helpers
// ---------------------------------------------------------------------------
__device__ __forceinline__ uint32_t f2tf(float f) {
    uint32_t u;
    asm("cvt.rna.tf32.f32 %0, %1;" : "=r"(u) : "f"(f));
    return u;
}
__device__ __forceinline__ float f2tf_f(float f) {
    return __uint_as_float(f2tf(f));
}

// D = A(16x8, tf32 row) * B(8x8, tf32 col) + D  (f32 accum)
__device__ __forceinline__ void mma8(float* c, const uint32_t* a,
                                     uint32_t b0, uint32_t b1) {
    asm volatile(
        "mma.sync.aligned.m16n8k8.row.col.f32.tf32.tf32.f32 "
        "{%0,%1,%2,%3},{%4,%5,%6,%7},{%8,%9},{%0,%1,%2,%3};\n"
        : "+f"(c[0]), "+f"(c[1]), "+f"(c[2]), "+f"(c[3])
        : "r"(a[0]), "r"(a[1]), "r"(a[2]), "r"(a[3]), "r"(b0), "r"(b1));
}

// ---------------------------------------------------------------------------
// GEMM: C[M][1024] = X[M][1024] @ W[1024][1024]^T + bias   (tf32 mma)
// BM=128, BN=128, BK=16. 256 threads = 8 warps (2 x 4), warp tile 64x32.
// head_split=1: write [B, H, S, Dh]; else row-major [M, D].
// ---------------------------------------------------------------------------
#define GS 20   // smem k-stride (conflict-free fragment loads)

__global__ __launch_bounds__(256)
void gemm_tf32(const float* __restrict__ X,
               const float* __restrict__ W,
               const float* __restrict__ bias,
               float* __restrict__ outp,
               int head_split)
{
    __shared__ float Xs[128 * GS];
    __shared__ float Ws[128 * GS];

    const int t    = threadIdx.x;
    const int m0   = blockIdx.y * 128;
    const int n0   = blockIdx.x * 128;
    const int lane = t & 31;
    const int w    = t >> 5;
    const int g    = lane >> 2;      // 0..7
    const int tg   = lane & 3;       // 0..3
    const int wr   = w >> 2;         // 0..1 : 64 rows of M
    const int wc   = w & 3;          // 0..3 : 32 cols of N

    const int lr = t >> 1;           // 0..127 row to load
    const int lc = (t & 1) * 8;      // 0 or 8

    float acc[4][4][4];
    #pragma unroll
    for (int i = 0; i < 4; i++)
        #pragma unroll
        for (int j = 0; j < 4; j++)
            #pragma unroll
            for (int r = 0; r < 4; r++) acc[i][j][r] = 0.f;

    for (int k0 = 0; k0 < D_MODEL; k0 += 16) {
        float4 x0 = *(const float4*)&X[(size_t)(m0 + lr) * D_MODEL + k0 + lc];
        float4 x1 = *(const float4*)&X[(size_t)(m0 + lr) * D_MODEL + k0 + lc + 4];
        float4 w0 = *(const float4*)&W[(size_t)(n0 + lr) * D_MODEL + k0 + lc];
        float4 w1 = *(const float4*)&W[(size_t)(n0 + lr) * D_MODEL + k0 + lc + 4];
        __syncthreads();
        {
            float4 c0 = make_float4(f2tf_f(x0.x), f2tf_f(x0.y), f2tf_f(x0.z), f2tf_f(x0.w));
            float4 c1 = make_float4(f2tf_f(x1.x), f2tf_f(x1.y), f2tf_f(x1.z), f2tf_f(x1.w));
            *(float4*)&Xs[lr * GS + lc]     = c0;
            *(float4*)&Xs[lr * GS + lc + 4] = c1;
            float4 d0 = make_float4(f2tf_f(w0.x), f2tf_f(w0.y), f2tf_f(w0.z), f2tf_f(w0.w));
            float4 d1 = make_float4(f2tf_f(w1.x), f2tf_f(w1.y), f2tf_f(w1.z), f2tf_f(w1.w));
            *(float4*)&Ws[lr * GS + lc]     = d0;
            *(float4*)&Ws[lr * GS + lc + 4] = d1;
        }
        __syncthreads();

        #pragma unroll
        for (int kk = 0; kk < 2; kk++) {
            const int col = kk * 8 + tg;
            uint32_t a[4][4];
            #pragma unroll
            for (int i = 0; i < 4; i++) {
                const int base = wr * 64 + i * 16;
                a[i][0] = __float_as_uint(Xs[(base + g)     * GS + col]);
                a[i][1] = __float_as_uint(Xs[(base + g + 8) * GS + col]);
                a[i][2] = __float_as_uint(Xs[(base + g)     * GS + col + 4]);
                a[i][3] = __float_as_uint(Xs[(base + g + 8) * GS + col + 4]);
            }
            #pragma unroll
            for (int j = 0; j < 4; j++) {
                const int nb = wc * 32 + j * 8;
                uint32_t b0 = __float_as_uint(Ws[(nb + g) * GS + col]);
                uint32_t b1 = __float_as_uint(Ws[(nb + g) * GS + col + 4]);
                #pragma unroll
                for (int i = 0; i < 4; i++)
                    mma8(acc[i][j], a[i], b0, b1);
            }
        }
    }

    // Epilogue
    #pragma unroll
    for (int j = 0; j < 4; j++) {
        const int col = n0 + wc * 32 + j * 8 + 2 * tg;
        const float bz0 = bias[col];
        const float bz1 = bias[col + 1];
        #pragma unroll
        for (int i = 0; i < 4; i++) {
            const int row0 = m0 + wr * 64 + i * 16 + g;
            const int row1 = row0 + 8;
            float2 v0 = make_float2(acc[i][j][0] + bz0, acc[i][j][1] + bz1);
            float2 v1 = make_float2(acc[i][j][2] + bz0, acc[i][j][3] + bz1);
            if (head_split) {
                const int hh = col >> 6;
                const int dd = col & (HEAD_DIM - 1);
                {
                    const int b = row0 >> 11, s = row0 & (SEQ - 1);
                    *(float2*)&outp[(((size_t)(b * N_HEADS + hh) * SEQ + s)) * HEAD_DIM + dd] = v0;
                }
                {
                    const int b = row1 >> 11, s = row1 & (SEQ - 1);
                    *(float2*)&outp[(((size_t)(b * N_HEADS + hh) * SEQ + s)) * HEAD_DIM + dd] = v1;
                }
            } else {
                *(float2*)&outp[(size_t)row0 * D_MODEL + col] = v0;
                *(float2*)&outp[(size_t)row1 * D_MODEL + col] = v1;
            }
        }
    }
}

// ---------------------------------------------------------------------------
// Fused attention per (b, h, 16-q-row tile), tf32 mma for QK^T and PV.
// ---------------------------------------------------------------------------
#define QT 16
#define KT 128
#define P_STRIDE  2052
#define QS_STRIDE 68
#define KV_STRIDE 68
#define SM_P_F  (QT * P_STRIDE)        // 32832
#define SM_Q_F  (QT * QS_STRIDE)       // 1088
#define SM_KV_F (KT * KV_STRIDE)       // 8704
#define SMEM_BYTES ((SM_P_F + SM_Q_F + SM_KV_F) * 4)   // 170,496

__global__ __launch_bounds__(256)
void attn_kernel(float* __restrict__ out_all)
{
    const int qtile = blockIdx.x;    // 0..127
    const int h     = blockIdx.y;    // 0..15
    const int b     = blockIdx.z;    // 0..1
    const int q0    = qtile * QT;
    const int t     = threadIdx.x;   // 0..255
    const int lane  = t & 31;
    const int w     = t >> 5;        // warp 0..7
    const int g     = lane >> 2;     // 0..7
    const int tg    = lane & 3;      // 0..3

    extern __shared__ float sm[];
    float* P   = sm;                 // [QT][P_STRIDE]
    float* Qs  = sm + SM_P_F;        // [QT][QS_STRIDE] (tf32-rounded, pre-scaled)
    float* KVs = Qs + SM_Q_F;        // [KT][KV_STRIDE]

    const size_t headBase = (size_t)(b * N_HEADS + h) * SEQ * HEAD_DIM;
    const float* Qh = g_Q + headBase + (size_t)q0 * HEAD_DIM;
    const float* Kh = g_K + headBase;
    const float* Vh = g_V + headBase;

    // Load Q tile (16x64), scale, round to tf32
    {
        const int idx = t * 4;
        const int qi = idx >> 6, d = idx & 63;
        float4 qv = *(const float4*)&Qh[(size_t)qi * HEAD_DIM + d];
        float4 cv = make_float4(f2tf_f(qv.x * SCALE_F), f2tf_f(qv.y * SCALE_F),
                                f2tf_f(qv.z * SCALE_F), f2tf_f(qv.w * SCALE_F));
        *(float4*)&Qs[qi * QS_STRIDE + d] = cv;
    }
    __syncthreads();

    // Q fragments (A operand, m16 x k8 per kstep), resident all of phase 1
    uint32_t qa[8][4];
    #pragma unroll
    for (int kk = 0; kk < 8; kk++) {
        const int col = kk * 8 + tg;
        qa[kk][0] = __float_as_uint(Qs[g       * QS_STRIDE + col]);
        qa[kk][1] = __float_as_uint(Qs[(g + 8) * QS_STRIDE + col]);
        qa[kk][2] = __float_as_uint(Qs[g       * QS_STRIDE + col + 4]);
        qa[kk][3] = __float_as_uint(Qs[(g + 8) * QS_STRIDE + col + 4]);
    }

    // ---- Phase 1: scores = Q @ K^T -> P ----
    for (int k0 = 0; k0 < SEQ; k0 += KT) {
        __syncthreads();
        #pragma unroll
        for (int rep = 0; rep < 8; rep++) {
            const int idx = rep * 256 + t;
            const int kl = idx >> 4, c4 = (idx & 15) * 4;
            float4 kv = *(const float4*)&Kh[(size_t)(k0 + kl) * HEAD_DIM + c4];
            float4 cv = make_float4(f2tf_f(kv.x), f2tf_f(kv.y), f2tf_f(kv.z), f2tf_f(kv.w));
            *(float4*)&KVs[kl * KV_STRIDE + c4] = cv;
        }
        __syncthreads();

        #pragma unroll
        for (int j = 0; j < 2; j++) {
            const int nb = w * 16 + j * 8;      // this warp's 8 keys
            float c[4] = {0.f, 0.f, 0.f, 0.f};
            #pragma unroll
            for (int kk = 0; kk < 8; kk++) {
                const int col = kk * 8 + tg;
                uint32_t b0 = __float_as_uint(KVs[(nb + g) * KV_STRIDE + col]);
                uint32_t b1 = __float_as_uint(KVs[(nb + g) * KV_STRIDE + col + 4]);
                mma8(c, qa[kk], b0, b1);
            }
            const int kc = k0 + nb + 2 * tg;
            *(float2*)&P[g       * P_STRIDE + kc] = make_float2(c[0], c[1]);
            *(float2*)&P[(g + 8) * P_STRIDE + kc] = make_float2(c[2], c[3]);
        }
    }
    __syncthreads();

    // ---- Phase 2: softmax rows, write attn to gmem, keep probs in P ----
    {
        float* attn = out_all + OUT_ELEMS;
        const size_t attnBase = ((size_t)(b * N_HEADS + h) * SEQ + q0) * SEQ;
        for (int qi = w; qi < QT; qi += 8) {
            float* row = P + qi * P_STRIDE;
            float mx = -1e30f;
            for (int k = lane; k < SEQ; k += 32) mx = fmaxf(mx, row[k]);
            #pragma unroll
            for (int off = 16; off; off >>= 1)
                mx = fmaxf(mx, __shfl_xor_sync(0xFFFFFFFFu, mx, off));

            float sum = 0.f;
            for (int k = lane * 4; k < SEQ; k += 128) {
                float4 s4 = *(float4*)&row[k];
                s4.x = __expf(s4.x - mx);
                s4.y = __expf(s4.y - mx);
                s4.z = __expf(s4.z - mx);
                s4.w = __expf(s4.w - mx);
                sum += s4.x + s4.y + s4.z + s4.w;
                *(float4*)&row[k] = s4;
            }
            #pragma unroll
            for (int off = 16; off; off >>= 1)
                sum += __shfl_xor_sync(0xFFFFFFFFu, sum, off);
            const float inv = 1.f / sum;

            float* arow = attn + attnBase + (size_t)qi * SEQ;
            for (int k = lane * 4; k < SEQ; k += 128) {
                float4 s4 = *(float4*)&row[k];
                s4.x *= inv; s4.y *= inv; s4.z *= inv; s4.w *= inv;
                *(float4*)&row[k]  = s4;   // probs for PV phase
                *(float4*)&arow[k] = s4;   // attn output (fp32 exact)
            }
        }
    }
    __syncthreads();

    // ---- Phase 3: O = P @ V (k-split across warps, then reduce) ----
    float o[8][4];
    #pragma unroll
    for (int j = 0; j < 8; j++)
        #pragma unroll
        for (int r = 0; r < 4; r++) o[j][r] = 0.f;

    for (int kt = 0; kt < 16; kt++) {
        const int k0 = kt * KT;
        __syncthreads();
        #pragma unroll
        for (int rep = 0; rep < 8; rep++) {
            const int idx = rep * 256 + t;
            const int kl = idx >> 4, c4 = (idx & 15) * 4;
            float4 vv = *(const float4*)&Vh[(size_t)(k0 + kl) * HEAD_DIM + c4];
            float4 cv = make_float4(f2tf_f(vv.x), f2tf_f(vv.y), f2tf_f(vv.z), f2tf_f(vv.w));
            *(float4*)&KVs[kl * KV_STRIDE + c4] = cv;
        }
        __syncthreads();

        #pragma unroll
        for (int ks = 0; ks < 2; ks++) {
            const int kb = w * 16 + ks * 8;     // warp's key slice in this tile
            uint32_t a[4];
            a[0] = f2tf(P[g       * P_STRIDE + k0 + kb + tg]);
            a[1] = f2tf(P[(g + 8) * P_STRIDE + k0 + kb + tg]);
            a[2] = f2tf(P[g       * P_STRIDE + k0 + kb + tg + 4]);
            a[3] = f2tf(P[(g + 8) * P_STRIDE + k0 + kb + tg + 4]);
            #pragma unroll
            for (int j = 0; j < 8; j++) {
                const int nb = j * 8;
                uint32_t b0 = __float_as_uint(KVs[(kb + tg)     * KV_STRIDE + nb + g]);
                uint32_t b1 = __float_as_uint(KVs[(kb + tg + 4) * KV_STRIDE + nb + g]);
                mma8(o[j], a, b0, b1);
            }
        }
    }
    __syncthreads();

    // Stage per-warp partials into P region: Ored[w][16][QS_STRIDE]
    float* Ored = P;
    #pragma unroll
    for (int j = 0; j < 8; j++) {
        const int nb = j * 8 + 2 * tg;
        *(float2*)&Ored[(w * 16 + g)     * QS_STRIDE + nb] = make_float2(o[j][0], o[j][1]);
        *(float2*)&Ored[(w * 16 + g + 8) * QS_STRIDE + nb] = make_float2(o[j][2], o[j][3]);
    }
    __syncthreads();

    // Reduce 8 partials; write ctx in [B, S, H*Dh] layout
    {
        const int e = t * 4;
        const int qi = e >> 6, d = e & 63;
        float4 s = make_float4(0.f, 0.f, 0.f, 0.f);
        #pragma unroll
        for (int ww = 0; ww < 8; ww++) {
            float4 p = *(float4*)&Ored[(ww * 16 + qi) * QS_STRIDE + d];
            s.x += p.x; s.y += p.y; s.z += p.z; s.w += p.w;
        }
        const size_t r = (size_t)(b * SEQ + q0 + qi) * D_MODEL + h * HEAD_DIM + d;
        *(float4*)&g_ctx[r] = s;
    }
}

// ---------------------------------------------------------------------------
extern "C" void kernel_launch(void* const* d_in, const int* in_sizes, int n_in,
                              void* d_out, int out_size)
{
    const float* q  = (const float*)d_in[0];
    const float* k  = (const float*)d_in[1];
    const float* v  = (const float*)d_in[2];
    const float* Wq = (const float*)d_in[3];
    const float* bq = (const float*)d_in[4];
    const float* Wk = (const float*)d_in[5];
    const float* bk = (const float*)d_in[6];
    const float* Wv = (const float*)d_in[7];
    const float* bv = (const float*)d_in[8];
    const float* Wo = (const float*)d_in[9];
    const float* bo = (const float*)d_in[10];
    float* out = (float*)d_out;

    float *Qp, *Kp, *Vp, *Cp;
    cudaGetSymbolAddress((void**)&Qp, g_Q);
    cudaGetSymbolAddress((void**)&Kp, g_K);
    cudaGetSymbolAddress((void**)&Vp, g_V);
    cudaGetSymbolAddress((void**)&Cp, g_ctx);

    cudaFuncSetAttribute(attn_kernel,
                         cudaFuncAttributeMaxDynamicSharedMemorySize, SMEM_BYTES);

    dim3 ggrid(D_MODEL / 128, M_ROWS / 128);   // (8, 32)
    gemm_tf32<<<ggrid, 256>>>(q, Wq, bq, Qp, 1);
    gemm_tf32<<<ggrid, 256>>>(k, Wk, bk, Kp, 1);
    gemm_tf32<<<ggrid, 256>>>(v, Wv, bv, Vp, 1);

    attn_kernel<<<dim3(SEQ / QT, N_HEADS, BATCH), 256, SMEM_BYTES>>>(out);

    gemm_tf32<<<ggrid, 256>>>(Cp, Wo, bo, out, 0);
}

// round 3
// speedup vs baseline: 3.5063x; 1.6824x over previous
#include <cuda_runtime.h>
#include <math.h>
#include <stdint.h>

// Problem constants
#define D_MODEL   1024
#define N_HEADS   16
#define HEAD_DIM  64
#define BATCH     2
#define SEQ       2048
#define M_ROWS    (BATCH * SEQ)                    // 4096
#define OUT_ELEMS ((size_t)BATCH * SEQ * D_MODEL)  // 4,194,304
#define SCALE_F   0.125f                           // 64^-0.5

// Scratch (device globals; no allocation allowed)
__device__ float g_Q[BATCH * N_HEADS * SEQ * HEAD_DIM];
__device__ float g_K[BATCH * N_HEADS * SEQ * HEAD_DIM];
__device__ float g_V[BATCH * N_HEADS * SEQ * HEAD_DIM];
__device__ float g_ctx[BATCH * SEQ * D_MODEL];

// ---------------------------------------------------------------------------
// tf32 helpers
// ---------------------------------------------------------------------------
__device__ __forceinline__ uint32_t f2tf(float f) {
    uint32_t u;
    asm("cvt.rna.tf32.f32 %0, %1;" : "=r"(u) : "f"(f));
    return u;
}
__device__ __forceinline__ float f2tf_f(float f) {
    return __uint_as_float(f2tf(f));
}
__device__ __forceinline__ float4 tf4(float4 v) {
    return make_float4(f2tf_f(v.x), f2tf_f(v.y), f2tf_f(v.z), f2tf_f(v.w));
}

// D = A(16x8, tf32 row) * B(8x8, tf32 col) + D  (f32 accum)
__device__ __forceinline__ void mma8(float* c, const uint32_t* a,
                                     uint32_t b0, uint32_t b1) {
    asm volatile(
        "mma.sync.aligned.m16n8k8.row.col.f32.tf32.tf32.f32 "
        "{%0,%1,%2,%3},{%4,%5,%6,%7},{%8,%9},{%0,%1,%2,%3};\n"
        : "+f"(c[0]), "+f"(c[1]), "+f"(c[2]), "+f"(c[3])
        : "r"(a[0]), "r"(a[1]), "r"(a[2]), "r"(a[3]), "r"(b0), "r"(b1));
}

// ---------------------------------------------------------------------------
// GEMM: C[M][1024] = X[M][1024] @ W[1024][1024]^T + bias   (tf32 mma)
// BM=128, BN=128, BK=16. 256 threads = 8 warps (2 x 4), warp tile 64x32.
// head_split=1: write [B, H, S, Dh]; else row-major [M, D].
// ---------------------------------------------------------------------------
#define GS 20   // smem k-stride

__global__ __launch_bounds__(256)
void gemm_tf32(const float* __restrict__ X,
               const float* __restrict__ W,
               const float* __restrict__ bias,
               float* __restrict__ outp,
               int head_split)
{
    __shared__ float Xs[128 * GS];
    __shared__ float Ws[128 * GS];

    const int t    = threadIdx.x;
    const int m0   = blockIdx.y * 128;
    const int n0   = blockIdx.x * 128;
    const int lane = t & 31;
    const int w    = t >> 5;
    const int g    = lane >> 2;
    const int tg   = lane & 3;
    const int wr   = w >> 2;
    const int wc   = w & 3;

    const int lr = t >> 1;
    const int lc = (t & 1) * 8;

    float acc[4][4][4];
    #pragma unroll
    for (int i = 0; i < 4; i++)
        #pragma unroll
        for (int j = 0; j < 4; j++)
            #pragma unroll
            for (int r = 0; r < 4; r++) acc[i][j][r] = 0.f;

    for (int k0 = 0; k0 < D_MODEL; k0 += 16) {
        float4 x0 = *(const float4*)&X[(size_t)(m0 + lr) * D_MODEL + k0 + lc];
        float4 x1 = *(const float4*)&X[(size_t)(m0 + lr) * D_MODEL + k0 + lc + 4];
        float4 w0 = *(const float4*)&W[(size_t)(n0 + lr) * D_MODEL + k0 + lc];
        float4 w1 = *(const float4*)&W[(size_t)(n0 + lr) * D_MODEL + k0 + lc + 4];
        __syncthreads();
        *(float4*)&Xs[lr * GS + lc]     = tf4(x0);
        *(float4*)&Xs[lr * GS + lc + 4] = tf4(x1);
        *(float4*)&Ws[lr * GS + lc]     = tf4(w0);
        *(float4*)&Ws[lr * GS + lc + 4] = tf4(w1);
        __syncthreads();

        #pragma unroll
        for (int kk = 0; kk < 2; kk++) {
            const int col = kk * 8 + tg;
            uint32_t a[4][4];
            #pragma unroll
            for (int i = 0; i < 4; i++) {
                const int base = wr * 64 + i * 16;
                a[i][0] = __float_as_uint(Xs[(base + g)     * GS + col]);
                a[i][1] = __float_as_uint(Xs[(base + g + 8) * GS + col]);
                a[i][2] = __float_as_uint(Xs[(base + g)     * GS + col + 4]);
                a[i][3] = __float_as_uint(Xs[(base + g + 8) * GS + col + 4]);
            }
            #pragma unroll
            for (int j = 0; j < 4; j++) {
                const int nb = wc * 32 + j * 8;
                uint32_t b0 = __float_as_uint(Ws[(nb + g) * GS + col]);
                uint32_t b1 = __float_as_uint(Ws[(nb + g) * GS + col + 4]);
                #pragma unroll
                for (int i = 0; i < 4; i++)
                    mma8(acc[i][j], a[i], b0, b1);
            }
        }
    }

    #pragma unroll
    for (int j = 0; j < 4; j++) {
        const int col = n0 + wc * 32 + j * 8 + 2 * tg;
        const float bz0 = bias[col];
        const float bz1 = bias[col + 1];
        #pragma unroll
        for (int i = 0; i < 4; i++) {
            const int row0 = m0 + wr * 64 + i * 16 + g;
            const int row1 = row0 + 8;
            float2 v0 = make_float2(acc[i][j][0] + bz0, acc[i][j][1] + bz1);
            float2 v1 = make_float2(acc[i][j][2] + bz0, acc[i][j][3] + bz1);
            if (head_split) {
                const int hh = col >> 6;
                const int dd = col & (HEAD_DIM - 1);
                {
                    const int b = row0 >> 11, s = row0 & (SEQ - 1);
                    *(float2*)&outp[(((size_t)(b * N_HEADS + hh) * SEQ + s)) * HEAD_DIM + dd] = v0;
                }
                {
                    const int b = row1 >> 11, s = row1 & (SEQ - 1);
                    *(float2*)&outp[(((size_t)(b * N_HEADS + hh) * SEQ + s)) * HEAD_DIM + dd] = v1;
                }
            } else {
                *(float2*)&outp[(size_t)row0 * D_MODEL + col] = v0;
                *(float2*)&outp[(size_t)row1 * D_MODEL + col] = v1;
            }
        }
    }
}

// ---------------------------------------------------------------------------
// Scores: S[bh][m][n] = SCALE * Q[bh][m] . K[bh][n]  (M=N=2048, K=64 one-shot)
// Block 128x128, 256 threads, warp tile 64x32. Writes raw scores to attn region.
// ---------------------------------------------------------------------------
#define SS 68
#define SCORES_SMEM (2 * 128 * SS * 4)   // 69,632 B

__global__ __launch_bounds__(256)
void scores_kernel(float* __restrict__ attnOut)
{
    const int n0 = blockIdx.x * 128;
    const int m0 = blockIdx.y * 128;
    const int bh = blockIdx.z;

    extern __shared__ float sm[];
    float* Qs = sm;              // [128][SS]
    float* Ks = sm + 128 * SS;   // [128][SS]

    const size_t hb = (size_t)bh * SEQ * HEAD_DIM;
    const float* Qg = g_Q + hb + (size_t)m0 * HEAD_DIM;
    const float* Kg = g_K + hb + (size_t)n0 * HEAD_DIM;

    const int t = threadIdx.x, lane = t & 31, w = t >> 5;
    const int g = lane >> 2, tg = lane & 3;
    const int wr = w >> 2, wc = w & 3;

    #pragma unroll
    for (int rep = 0; rep < 8; rep++) {
        const int idx = rep * 1024 + t * 4;
        const int r = idx >> 6, c = idx & 63;
        float4 qv = *(const float4*)&Qg[(size_t)r * HEAD_DIM + c];
        qv.x *= SCALE_F; qv.y *= SCALE_F; qv.z *= SCALE_F; qv.w *= SCALE_F;
        *(float4*)&Qs[r * SS + c] = tf4(qv);
        float4 kv = *(const float4*)&Kg[(size_t)r * HEAD_DIM + c];
        *(float4*)&Ks[r * SS + c] = tf4(kv);
    }
    __syncthreads();

    float acc[4][4][4];
    #pragma unroll
    for (int i = 0; i < 4; i++)
        #pragma unroll
        for (int j = 0; j < 4; j++)
            #pragma unroll
            for (int r = 0; r < 4; r++) acc[i][j][r] = 0.f;

    #pragma unroll
    for (int kk = 0; kk < 8; kk++) {
        const int col = kk * 8 + tg;
        uint32_t a[4][4];
        #pragma unroll
        for (int i = 0; i < 4; i++) {
            const int base = wr * 64 + i * 16;
            a[i][0] = __float_as_uint(Qs[(base + g)     * SS + col]);
            a[i][1] = __float_as_uint(Qs[(base + g + 8) * SS + col]);
            a[i][2] = __float_as_uint(Qs[(base + g)     * SS + col + 4]);
            a[i][3] = __float_as_uint(Qs[(base + g + 8) * SS + col + 4]);
        }
        #pragma unroll
        for (int j = 0; j < 4; j++) {
            const int nb = wc * 32 + j * 8;
            uint32_t b0 = __float_as_uint(Ks[(nb + g) * SS + col]);
            uint32_t b1 = __float_as_uint(Ks[(nb + g) * SS + col + 4]);
            #pragma unroll
            for (int i = 0; i < 4; i++)
                mma8(acc[i][j], a[i], b0, b1);
        }
    }

    float* Sout = attnOut + (size_t)bh * SEQ * SEQ;
    #pragma unroll
    for (int j = 0; j < 4; j++) {
        const int col = n0 + wc * 32 + j * 8 + 2 * tg;
        #pragma unroll
        for (int i = 0; i < 4; i++) {
            const int row0 = m0 + wr * 64 + i * 16 + g;
            *(float2*)&Sout[(size_t)row0 * SEQ + col] =
                make_float2(acc[i][j][0], acc[i][j][1]);
            *(float2*)&Sout[(size_t)(row0 + 8) * SEQ + col] =
                make_float2(acc[i][j][2], acc[i][j][3]);
        }
    }
}

// ---------------------------------------------------------------------------
// Softmax: in-place per row of the attn region. One block per row; row lives
// entirely in registers (8 floats/thread).
// ---------------------------------------------------------------------------
__global__ __launch_bounds__(256)
void softmax_kernel(float* __restrict__ attnOut)
{
    float* row = attnOut + (size_t)blockIdx.x * SEQ;
    const int t = threadIdx.x, lane = t & 31, w = t >> 5;
    __shared__ float red[8];

    float4 v0 = *(float4*)&row[t * 8];
    float4 v1 = *(float4*)&row[t * 8 + 4];

    float mx = fmaxf(fmaxf(fmaxf(v0.x, v0.y), fmaxf(v0.z, v0.w)),
                     fmaxf(fmaxf(v1.x, v1.y), fmaxf(v1.z, v1.w)));
    #pragma unroll
    for (int off = 16; off; off >>= 1)
        mx = fmaxf(mx, __shfl_xor_sync(0xFFFFFFFFu, mx, off));
    if (lane == 0) red[w] = mx;
    __syncthreads();
    mx = red[0];
    #pragma unroll
    for (int i = 1; i < 8; i++) mx = fmaxf(mx, red[i]);
    __syncthreads();

    v0.x = __expf(v0.x - mx); v0.y = __expf(v0.y - mx);
    v0.z = __expf(v0.z - mx); v0.w = __expf(v0.w - mx);
    v1.x = __expf(v1.x - mx); v1.y = __expf(v1.y - mx);
    v1.z = __expf(v1.z - mx); v1.w = __expf(v1.w - mx);

    float sum = v0.x + v0.y + v0.z + v0.w + v1.x + v1.y + v1.z + v1.w;
    #pragma unroll
    for (int off = 16; off; off >>= 1)
        sum += __shfl_xor_sync(0xFFFFFFFFu, sum, off);
    if (lane == 0) red[w] = sum;
    __syncthreads();
    sum = red[0];
    #pragma unroll
    for (int i = 1; i < 8; i++) sum += red[i];

    const float inv = 1.f / sum;
    v0.x *= inv; v0.y *= inv; v0.z *= inv; v0.w *= inv;
    v1.x *= inv; v1.y *= inv; v1.z *= inv; v1.w *= inv;
    *(float4*)&row[t * 8]     = v0;
    *(float4*)&row[t * 8 + 4] = v1;
}

// ---------------------------------------------------------------------------
// PV: ctx[bh][m][0:64] = P[bh][m][:] @ V[bh][:][0:64]
// Block: 128 m-rows x full N=64, k-loop in 128 chunks. Every attn element read once.
// ---------------------------------------------------------------------------
#define PS 132
#define VS 68
#define PV_SMEM ((128 * PS + 128 * VS) * 4)   // 102,400 B

__global__ __launch_bounds__(256)
void pv_kernel(const float* __restrict__ attnOut)
{
    const int m0 = blockIdx.x * 128;
    const int bh = blockIdx.y;
    const int bb = bh >> 4, hh = bh & 15;

    extern __shared__ float sm[];
    float* Ps = sm;              // [128][PS]
    float* Vs = sm + 128 * PS;   // [128][VS]

    const float* Pg = attnOut + (size_t)bh * SEQ * SEQ + (size_t)m0 * SEQ;
    const float* Vg = g_V + (size_t)bh * SEQ * HEAD_DIM;

    const int t = threadIdx.x, lane = t & 31, w = t >> 5;
    const int g = lane >> 2, tg = lane & 3;

    float acc[8][4];
    #pragma unroll
    for (int j = 0; j < 8; j++)
        #pragma unroll
        for (int r = 0; r < 4; r++) acc[j][r] = 0.f;

    for (int k0 = 0; k0 < SEQ; k0 += 128) {
        __syncthreads();
        #pragma unroll
        for (int rep = 0; rep < 16; rep++) {
            const int idx = rep * 1024 + t * 4;
            const int r = idx >> 7, c = idx & 127;
            float4 p = *(const float4*)&Pg[(size_t)r * SEQ + k0 + c];
            *(float4*)&Ps[r * PS + c] = tf4(p);
        }
        #pragma unroll
        for (int rep = 0; rep < 8; rep++) {
            const int idx = rep * 1024 + t * 4;
            const int r = idx >> 6, c = idx & 63;
            float4 vv = *(const float4*)&Vg[(size_t)(k0 + r) * HEAD_DIM + c];
            *(float4*)&Vs[r * VS + c] = tf4(vv);
        }
        __syncthreads();

        #pragma unroll
        for (int kk = 0; kk < 16; kk++) {
            const int kb = kk * 8;
            uint32_t a[4];
            a[0] = __float_as_uint(Ps[(w * 16 + g)     * PS + kb + tg]);
            a[1] = __float_as_uint(Ps[(w * 16 + g + 8) * PS + kb + tg]);
            a[2] = __float_as_uint(Ps[(w * 16 + g)     * PS + kb + tg + 4]);
            a[3] = __float_as_uint(Ps[(w * 16 + g + 8) * PS + kb + tg + 4]);
            #pragma unroll
            for (int j = 0; j < 8; j++) {
                const int nb = j * 8;
                uint32_t b0 = __float_as_uint(Vs[(kb + tg)     * VS + nb + g]);
                uint32_t b1 = __float_as_uint(Vs[(kb + tg + 4) * VS + nb + g]);
                mma8(acc[j], a, b0, b1);
            }
        }
    }

    // ctx layout [B, S, H*Dh]
    #pragma unroll
    for (int j = 0; j < 8; j++) {
        const int col = hh * HEAD_DIM + j * 8 + 2 * tg;
        const int row0 = m0 + w * 16 + g;
        const int row1 = row0 + 8;
        *(float2*)&g_ctx[(size_t)(bb * SEQ + row0) * D_MODEL + col] =
            make_float2(acc[j][0], acc[j][1]);
        *(float2*)&g_ctx[(size_t)(bb * SEQ + row1) * D_MODEL + col] =
            make_float2(acc[j][2], acc[j][3]);
    }
}

// ---------------------------------------------------------------------------
extern "C" void kernel_launch(void* const* d_in, const int* in_sizes, int n_in,
                              void* d_out, int out_size)
{
    const float* q  = (const float*)d_in[0];
    const float* k  = (const float*)d_in[1];
    const float* v  = (const float*)d_in[2];
    const float* Wq = (const float*)d_in[3];
    const float* bq = (const float*)d_in[4];
    const float* Wk = (const float*)d_in[5];
    const float* bk = (const float*)d_in[6];
    const float* Wv = (const float*)d_in[7];
    const float* bv = (const float*)d_in[8];
    const float* Wo = (const float*)d_in[9];
    const float* bo = (const float*)d_in[10];
    float* out  = (float*)d_out;
    float* attn = out + OUT_ELEMS;

    float *Qp, *Kp, *Vp, *Cp;
    cudaGetSymbolAddress((void**)&Qp, g_Q);
    cudaGetSymbolAddress((void**)&Kp, g_K);
    cudaGetSymbolAddress((void**)&Vp, g_V);
    cudaGetSymbolAddress((void**)&Cp, g_ctx);

    cudaFuncSetAttribute(scores_kernel,
                         cudaFuncAttributeMaxDynamicSharedMemorySize, SCORES_SMEM);
    cudaFuncSetAttribute(pv_kernel,
                         cudaFuncAttributeMaxDynamicSharedMemorySize, PV_SMEM);

    dim3 ggrid(D_MODEL / 128, M_ROWS / 128);   // (8, 32)
    gemm_tf32<<<ggrid, 256>>>(q, Wq, bq, Qp, 1);
    gemm_tf32<<<ggrid, 256>>>(k, Wk, bk, Kp, 1);
    gemm_tf32<<<ggrid, 256>>>(v, Wv, bv, Vp, 1);

    scores_kernel<<<dim3(SEQ / 128, SEQ / 128, BATCH * N_HEADS), 256, SCORES_SMEM>>>(attn);
    softmax_kernel<<<BATCH * N_HEADS * SEQ, 256>>>(attn);
    pv_kernel<<<dim3(SEQ / 128, BATCH * N_HEADS), 256, PV_SMEM>>>(attn);

    gemm_tf32<<<ggrid, 256>>>(Cp, Wo, bo, out, 0);
}

// round 4
// speedup vs baseline: 3.5520x; 1.0130x over previous
#include <cuda_runtime.h>
#include <math.h>
#include <stdint.h>

// Problem constants
#define D_MODEL   1024
#define N_HEADS   16
#define HEAD_DIM  64
#define BATCH     2
#define SEQ       2048
#define M_ROWS    (BATCH * SEQ)                    // 4096
#define OUT_ELEMS ((size_t)BATCH * SEQ * D_MODEL)  // 4,194,304
#define SCALE_F   0.125f                           // 64^-0.5
#define NBH       (BATCH * N_HEADS)                // 32
#define NTILES    (SEQ / 128)                      // 16

// Scratch (device globals; no allocation allowed)
__device__ float g_Q[BATCH * N_HEADS * SEQ * HEAD_DIM];
__device__ float g_K[BATCH * N_HEADS * SEQ * HEAD_DIM];
__device__ float g_V[BATCH * N_HEADS * SEQ * HEAD_DIM];
__device__ float g_ctx[BATCH * SEQ * D_MODEL];
__device__ float g_pmax[NBH * SEQ * NTILES];   // per (row, n-tile) max
__device__ float g_psum[NBH * SEQ * NTILES];   // per (row, n-tile) sum exp(s - tilemax)
__device__ float2 g_rstat[NBH * SEQ];          // per row: (rowmax, 1/rowsum)

// ---------------------------------------------------------------------------
// tf32 helpers
// ---------------------------------------------------------------------------
__device__ __forceinline__ uint32_t f2tf(float f) {
    uint32_t u;
    asm("cvt.rna.tf32.f32 %0, %1;" : "=r"(u) : "f"(f));
    return u;
}
__device__ __forceinline__ float f2tf_f(float f) {
    return __uint_as_float(f2tf(f));
}
__device__ __forceinline__ float4 tf4(float4 v) {
    return make_float4(f2tf_f(v.x), f2tf_f(v.y), f2tf_f(v.z), f2tf_f(v.w));
}

// D = A(16x8, tf32 row) * B(8x8, tf32 col) + D  (f32 accum)
__device__ __forceinline__ void mma8(float* c, const uint32_t* a,
                                     uint32_t b0, uint32_t b1) {
    asm volatile(
        "mma.sync.aligned.m16n8k8.row.col.f32.tf32.tf32.f32 "
        "{%0,%1,%2,%3},{%4,%5,%6,%7},{%8,%9},{%0,%1,%2,%3};\n"
        : "+f"(c[0]), "+f"(c[1]), "+f"(c[2]), "+f"(c[3])
        : "r"(a[0]), "r"(a[1]), "r"(a[2]), "r"(a[3]), "r"(b0), "r"(b1));
}

// ---------------------------------------------------------------------------
// GEMM: C[M][1024] = X[M][1024] @ W[1024][1024]^T + bias   (tf32 mma)
// BM=BN=128, BK=16, double-buffered smem, 1 sync/iter. 256 threads, 8 warps.
// ---------------------------------------------------------------------------
#define GS 20
#define GEMM_SMEM (4 * 128 * GS * 4)   // 2 stages x (Xs + Ws) = 81,920 B

__global__ __launch_bounds__(256, 2)
void gemm_tf32(const float* __restrict__ X,
               const float* __restrict__ W,
               const float* __restrict__ bias,
               float* __restrict__ outp,
               int head_split)
{
    extern __shared__ float sm[];
    float* Xb[2] = { sm,               sm + 2 * 128 * GS };
    float* Wb[2] = { sm + 128 * GS,    sm + 3 * 128 * GS };

    const int t    = threadIdx.x;
    const int m0   = blockIdx.y * 128;
    const int n0   = blockIdx.x * 128;
    const int lane = t & 31;
    const int w    = t >> 5;
    const int g    = lane >> 2;
    const int tg   = lane & 3;
    const int wr   = w >> 2;
    const int wc   = w & 3;

    const int lr = t >> 1;
    const int lc = (t & 1) * 8;

    const float* Xrow = &X[(size_t)(m0 + lr) * D_MODEL + lc];
    const float* Wrow = &W[(size_t)(n0 + lr) * D_MODEL + lc];

    float acc[4][4][4];
    #pragma unroll
    for (int i = 0; i < 4; i++)
        #pragma unroll
        for (int j = 0; j < 4; j++)
            #pragma unroll
            for (int r = 0; r < 4; r++) acc[i][j][r] = 0.f;

    // Prologue: stage k0=0 into buffer 0
    {
        float4 x0 = *(const float4*)&Xrow[0];
        float4 x1 = *(const float4*)&Xrow[4];
        float4 w0 = *(const float4*)&Wrow[0];
        float4 w1 = *(const float4*)&Wrow[4];
        *(float4*)&Xb[0][lr * GS + lc]     = tf4(x0);
        *(float4*)&Xb[0][lr * GS + lc + 4] = tf4(x1);
        *(float4*)&Wb[0][lr * GS + lc]     = tf4(w0);
        *(float4*)&Wb[0][lr * GS + lc + 4] = tf4(w1);
    }
    __syncthreads();

    #pragma unroll 1
    for (int it = 0; it < 64; it++) {
        float* Xs = Xb[it & 1];
        float* Ws = Wb[it & 1];

        float4 x0, x1, w0, w1;
        const bool pre = (it < 63);
        if (pre) {
            const int k0 = (it + 1) * 16;
            x0 = *(const float4*)&Xrow[k0];
            x1 = *(const float4*)&Xrow[k0 + 4];
            w0 = *(const float4*)&Wrow[k0];
            w1 = *(const float4*)&Wrow[k0 + 4];
        }

        #pragma unroll
        for (int kk = 0; kk < 2; kk++) {
            const int col = kk * 8 + tg;
            uint32_t a[4][4];
            #pragma unroll
            for (int i = 0; i < 4; i++) {
                const int base = wr * 64 + i * 16;
                a[i][0] = __float_as_uint(Xs[(base + g)     * GS + col]);
                a[i][1] = __float_as_uint(Xs[(base + g + 8) * GS + col]);
                a[i][2] = __float_as_uint(Xs[(base + g)     * GS + col + 4]);
                a[i][3] = __float_as_uint(Xs[(base + g + 8) * GS + col + 4]);
            }
            #pragma unroll
            for (int j = 0; j < 4; j++) {
                const int nb = wc * 32 + j * 8;
                uint32_t b0 = __float_as_uint(Ws[(nb + g) * GS + col]);
                uint32_t b1 = __float_as_uint(Ws[(nb + g) * GS + col + 4]);
                #pragma unroll
                for (int i = 0; i < 4; i++)
                    mma8(acc[i][j], a[i], b0, b1);
            }
        }

        if (pre) {
            float* Xn = Xb[(it + 1) & 1];
            float* Wn = Wb[(it + 1) & 1];
            *(float4*)&Xn[lr * GS + lc]     = tf4(x0);
            *(float4*)&Xn[lr * GS + lc + 4] = tf4(x1);
            *(float4*)&Wn[lr * GS + lc]     = tf4(w0);
            *(float4*)&Wn[lr * GS + lc + 4] = tf4(w1);
        }
        __syncthreads();
    }

    #pragma unroll
    for (int j = 0; j < 4; j++) {
        const int col = n0 + wc * 32 + j * 8 + 2 * tg;
        const float bz0 = bias[col];
        const float bz1 = bias[col + 1];
        #pragma unroll
        for (int i = 0; i < 4; i++) {
            const int row0 = m0 + wr * 64 + i * 16 + g;
            const int row1 = row0 + 8;
            float2 v0 = make_float2(acc[i][j][0] + bz0, acc[i][j][1] + bz1);
            float2 v1 = make_float2(acc[i][j][2] + bz0, acc[i][j][3] + bz1);
            if (head_split) {
                const int hh = col >> 6;
                const int dd = col & (HEAD_DIM - 1);
                {
                    const int b = row0 >> 11, s = row0 & (SEQ - 1);
                    *(float2*)&outp[(((size_t)(b * N_HEADS + hh) * SEQ + s)) * HEAD_DIM + dd] = v0;
                }
                {
                    const int b = row1 >> 11, s = row1 & (SEQ - 1);
                    *(float2*)&outp[(((size_t)(b * N_HEADS + hh) * SEQ + s)) * HEAD_DIM + dd] = v1;
                }
            } else {
                *(float2*)&outp[(size_t)row0 * D_MODEL + col] = v0;
                *(float2*)&outp[(size_t)row1 * D_MODEL + col] = v1;
            }
        }
    }
}

// ---------------------------------------------------------------------------
// Scores: S = SCALE * Q K^T  (raw, written to attn region), plus per-tile
// softmax partials (rowmax, sum exp(s - rowmax_tile)) from registers.
// ---------------------------------------------------------------------------
#define SS 68
#define SCORES_SMEM (2 * 128 * SS * 4)   // 69,632 B

__global__ __launch_bounds__(256, 2)
void scores_kernel(float* __restrict__ attnOut)
{
    const int n0 = blockIdx.x * 128;
    const int m0 = blockIdx.y * 128;
    const int bh = blockIdx.z;

    extern __shared__ float sm[];
    float* Qs = sm;
    float* Ks = sm + 128 * SS;

    const size_t hb = (size_t)bh * SEQ * HEAD_DIM;
    const float* Qg = g_Q + hb + (size_t)m0 * HEAD_DIM;
    const float* Kg = g_K + hb + (size_t)n0 * HEAD_DIM;

    const int t = threadIdx.x, lane = t & 31, w = t >> 5;
    const int g = lane >> 2, tg = lane & 3;
    const int wr = w >> 2, wc = w & 3;

    #pragma unroll
    for (int rep = 0; rep < 8; rep++) {
        const int idx = rep * 1024 + t * 4;
        const int r = idx >> 6, c = idx & 63;
        float4 qv = *(const float4*)&Qg[(size_t)r * HEAD_DIM + c];
        qv.x *= SCALE_F; qv.y *= SCALE_F; qv.z *= SCALE_F; qv.w *= SCALE_F;
        *(float4*)&Qs[r * SS + c] = tf4(qv);
        float4 kv = *(const float4*)&Kg[(size_t)r * HEAD_DIM + c];
        *(float4*)&Ks[r * SS + c] = tf4(kv);
    }
    __syncthreads();

    float acc[4][4][4];
    #pragma unroll
    for (int i = 0; i < 4; i++)
        #pragma unroll
        for (int j = 0; j < 4; j++)
            #pragma unroll
            for (int r = 0; r < 4; r++) acc[i][j][r] = 0.f;

    #pragma unroll
    for (int kk = 0; kk < 8; kk++) {
        const int col = kk * 8 + tg;
        uint32_t a[4][4];
        #pragma unroll
        for (int i = 0; i < 4; i++) {
            const int base = wr * 64 + i * 16;
            a[i][0] = __float_as_uint(Qs[(base + g)     * SS + col]);
            a[i][1] = __float_as_uint(Qs[(base + g + 8) * SS + col]);
            a[i][2] = __float_as_uint(Qs[(base + g)     * SS + col + 4]);
            a[i][3] = __float_as_uint(Qs[(base + g + 8) * SS + col + 4]);
        }
        #pragma unroll
        for (int j = 0; j < 4; j++) {
            const int nb = wc * 32 + j * 8;
            uint32_t b0 = __float_as_uint(Ks[(nb + g) * SS + col]);
            uint32_t b1 = __float_as_uint(Ks[(nb + g) * SS + col + 4]);
            #pragma unroll
            for (int i = 0; i < 4; i++)
                mma8(acc[i][j], a[i], b0, b1);
        }
    }

    // Write raw scores
    float* Sout = attnOut + (size_t)bh * SEQ * SEQ;
    #pragma unroll
    for (int j = 0; j < 4; j++) {
        const int col = n0 + wc * 32 + j * 8 + 2 * tg;
        #pragma unroll
        for (int i = 0; i < 4; i++) {
            const int row0 = m0 + wr * 64 + i * 16 + g;
            *(float2*)&Sout[(size_t)row0 * SEQ + col] =
                make_float2(acc[i][j][0], acc[i][j][1]);
            *(float2*)&Sout[(size_t)(row0 + 8) * SEQ + col] =
                make_float2(acc[i][j][2], acc[i][j][3]);
        }
    }

    // ---- softmax partials from registers ----
    __syncthreads();                 // done reading Qs/Ks; reuse smem
    float* stmax = sm;               // [128][4]
    float* stsum = sm + 512;         // [128][4]

    // phase A: tile-local row max
    #pragma unroll
    for (int i = 0; i < 4; i++) {
        float m0v = -1e30f, m1v = -1e30f;
        #pragma unroll
        for (int j = 0; j < 4; j++) {
            m0v = fmaxf(m0v, fmaxf(acc[i][j][0], acc[i][j][1]));
            m1v = fmaxf(m1v, fmaxf(acc[i][j][2], acc[i][j][3]));
        }
        m0v = fmaxf(m0v, __shfl_xor_sync(0xFFFFFFFFu, m0v, 1));
        m0v = fmaxf(m0v, __shfl_xor_sync(0xFFFFFFFFu, m0v, 2));
        m1v = fmaxf(m1v, __shfl_xor_sync(0xFFFFFFFFu, m1v, 1));
        m1v = fmaxf(m1v, __shfl_xor_sync(0xFFFFFFFFu, m1v, 2));
        if (tg == 0) {
            const int r0 = wr * 64 + i * 16 + g;
            stmax[r0 * 4 + wc]       = m0v;
            stmax[(r0 + 8) * 4 + wc] = m1v;
        }
    }
    __syncthreads();

    // phase B: sum exp(s - tile rowmax)
    #pragma unroll
    for (int i = 0; i < 4; i++) {
        const int r0 = wr * 64 + i * 16 + g;
        const float M0 = fmaxf(fmaxf(stmax[r0 * 4 + 0], stmax[r0 * 4 + 1]),
                               fmaxf(stmax[r0 * 4 + 2], stmax[r0 * 4 + 3]));
        const int r1 = r0 + 8;
        const float M1 = fmaxf(fmaxf(stmax[r1 * 4 + 0], stmax[r1 * 4 + 1]),
                               fmaxf(stmax[r1 * 4 + 2], stmax[r1 * 4 + 3]));
        float s0 = 0.f, s1 = 0.f;
        #pragma unroll
        for (int j = 0; j < 4; j++) {
            s0 += __expf(acc[i][j][0] - M0) + __expf(acc[i][j][1] - M0);
            s1 += __expf(acc[i][j][2] - M1) + __expf(acc[i][j][3] - M1);
        }
        s0 += __shfl_xor_sync(0xFFFFFFFFu, s0, 1);
        s0 += __shfl_xor_sync(0xFFFFFFFFu, s0, 2);
        s1 += __shfl_xor_sync(0xFFFFFFFFu, s1, 1);
        s1 += __shfl_xor_sync(0xFFFFFFFFu, s1, 2);
        if (tg == 0) {
            stsum[r0 * 4 + wc] = s0;
            stsum[r1 * 4 + wc] = s1;
        }
    }
    __syncthreads();

    if (t < 128) {
        const float M = fmaxf(fmaxf(stmax[t * 4 + 0], stmax[t * 4 + 1]),
                              fmaxf(stmax[t * 4 + 2], stmax[t * 4 + 3]));
        const float S = stsum[t * 4 + 0] + stsum[t * 4 + 1] +
                        stsum[t * 4 + 2] + stsum[t * 4 + 3];
        const size_t p = ((size_t)bh * SEQ + m0 + t) * NTILES + blockIdx.x;
        g_pmax[p] = M;
        g_psum[p] = S;
    }
}

// ---------------------------------------------------------------------------
// Combine partials -> per-row (rowmax, 1/rowsum)
// ---------------------------------------------------------------------------
__global__ __launch_bounds__(256)
void combine_kernel()
{
    const int row = blockIdx.x * 256 + threadIdx.x;   // 0 .. NBH*SEQ-1
    const float* pm = &g_pmax[(size_t)row * NTILES];
    const float* ps = &g_psum[(size_t)row * NTILES];

    float m[NTILES], s[NTILES];
    #pragma unroll
    for (int i = 0; i < NTILES; i += 4) {
        float4 a = *(const float4*)&pm[i];
        m[i] = a.x; m[i+1] = a.y; m[i+2] = a.z; m[i+3] = a.w;
        float4 b = *(const float4*)&ps[i];
        s[i] = b.x; s[i+1] = b.y; s[i+2] = b.z; s[i+3] = b.w;
    }
    float M = m[0];
    #pragma unroll
    for (int i = 1; i < NTILES; i++) M = fmaxf(M, m[i]);
    float l = 0.f;
    #pragma unroll
    for (int i = 0; i < NTILES; i++) l += s[i] * __expf(m[i] - M);
    g_rstat[row] = make_float2(M, 1.f / l);
}

// ---------------------------------------------------------------------------
// PV: applies softmax inline (p = exp(s - M) * inv), writes normalized attn
// back in place, and computes ctx = P @ V.
// ---------------------------------------------------------------------------
#define PS 132
#define VS 68
#define PV_SMEM ((128 * PS + 128 * VS) * 4)   // 102,400 B

__global__ __launch_bounds__(256, 2)
void pv_kernel(float* __restrict__ attnOut)
{
    const int m0 = blockIdx.x * 128;
    const int bh = blockIdx.y;
    const int bb = bh >> 4, hh = bh & 15;

    extern __shared__ float sm[];
    float* Ps = sm;
    float* Vs = sm + 128 * PS;

    float* Pg = attnOut + (size_t)bh * SEQ * SEQ + (size_t)m0 * SEQ;
    const float* Vg = g_V + (size_t)bh * SEQ * HEAD_DIM;
    const float2* rstat = &g_rstat[(size_t)bh * SEQ + m0];

    const int t = threadIdx.x, lane = t & 31, w = t >> 5;
    const int g = lane >> 2, tg = lane & 3;

    float acc[8][4];
    #pragma unroll
    for (int j = 0; j < 8; j++)
        #pragma unroll
        for (int r = 0; r < 4; r++) acc[j][r] = 0.f;

    for (int k0 = 0; k0 < SEQ; k0 += 128) {
        __syncthreads();
        #pragma unroll
        for (int rep = 0; rep < 16; rep++) {
            const int idx = rep * 1024 + t * 4;
            const int r = idx >> 7, c = idx & 127;
            const float2 st = rstat[r];
            float4 p = *(const float4*)&Pg[(size_t)r * SEQ + k0 + c];
            p.x = __expf(p.x - st.x) * st.y;
            p.y = __expf(p.y - st.x) * st.y;
            p.z = __expf(p.z - st.x) * st.y;
            p.w = __expf(p.w - st.x) * st.y;
            *(float4*)&Pg[(size_t)r * SEQ + k0 + c] = p;   // normalized attn out
            *(float4*)&Ps[r * PS + c] = tf4(p);
        }
        #pragma unroll
        for (int rep = 0; rep < 8; rep++) {
            const int idx = rep * 1024 + t * 4;
            const int r = idx >> 6, c = idx & 63;
            float4 vv = *(const float4*)&Vg[(size_t)(k0 + r) * HEAD_DIM + c];
            *(float4*)&Vs[r * VS + c] = tf4(vv);
        }
        __syncthreads();

        #pragma unroll
        for (int kk = 0; kk < 16; kk++) {
            const int kb = kk * 8;
            uint32_t a[4];
            a[0] = __float_as_uint(Ps[(w * 16 + g)     * PS + kb + tg]);
            a[1] = __float_as_uint(Ps[(w * 16 + g + 8) * PS + kb + tg]);
            a[2] = __float_as_uint(Ps[(w * 16 + g)     * PS + kb + tg + 4]);
            a[3] = __float_as_uint(Ps[(w * 16 + g + 8) * PS + kb + tg + 4]);
            #pragma unroll
            for (int j = 0; j < 8; j++) {
                const int nb = j * 8;
                uint32_t b0 = __float_as_uint(Vs[(kb + tg)     * VS + nb + g]);
                uint32_t b1 = __float_as_uint(Vs[(kb + tg + 4) * VS + nb + g]);
                mma8(acc[j], a, b0, b1);
            }
        }
    }

    #pragma unroll
    for (int j = 0; j < 8; j++) {
        const int col = hh * HEAD_DIM + j * 8 + 2 * tg;
        const int row0 = m0 + w * 16 + g;
        const int row1 = row0 + 8;
        *(float2*)&g_ctx[(size_t)(bb * SEQ + row0) * D_MODEL + col] =
            make_float2(acc[j][0], acc[j][1]);
        *(float2*)&g_ctx[(size_t)(bb * SEQ + row1) * D_MODEL + col] =
            make_float2(acc[j][2], acc[j][3]);
    }
}

// ---------------------------------------------------------------------------
extern "C" void kernel_launch(void* const* d_in, const int* in_sizes, int n_in,
                              void* d_out, int out_size)
{
    const float* q  = (const float*)d_in[0];
    const float* k  = (const float*)d_in[1];
    const float* v  = (const float*)d_in[2];
    const float* Wq = (const float*)d_in[3];
    const float* bq = (const float*)d_in[4];
    const float* Wk = (const float*)d_in[5];
    const float* bk = (const float*)d_in[6];
    const float* Wv = (const float*)d_in[7];
    const float* bv = (const float*)d_in[8];
    const float* Wo = (const float*)d_in[9];
    const float* bo = (const float*)d_in[10];
    float* out  = (float*)d_out;
    float* attn = out + OUT_ELEMS;

    float *Qp, *Kp, *Vp, *Cp;
    cudaGetSymbolAddress((void**)&Qp, g_Q);
    cudaGetSymbolAddress((void**)&Kp, g_K);
    cudaGetSymbolAddress((void**)&Vp, g_V);
    cudaGetSymbolAddress((void**)&Cp, g_ctx);

    cudaFuncSetAttribute(gemm_tf32,
                         cudaFuncAttributeMaxDynamicSharedMemorySize, GEMM_SMEM);
    cudaFuncSetAttribute(scores_kernel,
                         cudaFuncAttributeMaxDynamicSharedMemorySize, SCORES_SMEM);
    cudaFuncSetAttribute(pv_kernel,
                         cudaFuncAttributeMaxDynamicSharedMemorySize, PV_SMEM);

    dim3 ggrid(D_MODEL / 128, M_ROWS / 128);   // (8, 32)
    gemm_tf32<<<ggrid, 256, GEMM_SMEM>>>(q, Wq, bq, Qp, 1);
    gemm_tf32<<<ggrid, 256, GEMM_SMEM>>>(k, Wk, bk, Kp, 1);
    gemm_tf32<<<ggrid, 256, GEMM_SMEM>>>(v, Wv, bv, Vp, 1);

    scores_kernel<<<dim3(NTILES, NTILES, NBH), 256, SCORES_SMEM>>>(attn);
    combine_kernel<<<(NBH * SEQ) / 256, 256>>>();
    pv_kernel<<<dim3(NTILES, NBH), 256, PV_SMEM>>>(attn);

    gemm_tf32<<<ggrid, 256, GEMM_SMEM>>>(Cp, Wo, bo, out, 0);
}

// round 5
// speedup vs baseline: 4.3271x; 1.2182x over previous
#include <cuda_runtime.h>
#include <cuda_fp16.h>
#include <math.h>
#include <stdint.h>

// Problem constants
#define D_MODEL   1024
#define N_HEADS   16
#define HEAD_DIM  64
#define BATCH     2
#define SEQ       2048
#define M_ROWS    (BATCH * SEQ)                    // 4096
#define OUT_ELEMS ((size_t)BATCH * SEQ * D_MODEL)  // 4,194,304
#define SCALE_F   0.125f                           // 64^-0.5
#define NBH       (BATCH * N_HEADS)                // 32
#define NTILES    (SEQ / 128)                      // 16

// Scratch (device globals; no allocation allowed)
__device__ float g_Q[NBH * SEQ * HEAD_DIM];
__device__ float g_K[NBH * SEQ * HEAD_DIM];
__device__ float g_V[NBH * SEQ * HEAD_DIM];
__device__ float g_ctx[M_ROWS * D_MODEL];
__device__ float g_pmax[NBH * SEQ * NTILES];   // per (row, n-tile) max
__device__ float g_psum[NBH * SEQ * NTILES];   // per (row, n-tile) sum exp(s - tilemax)

// ---------------------------------------------------------------------------
// fp16 helpers
// ---------------------------------------------------------------------------
__device__ __forceinline__ uint32_t h2u(float a, float b) {
    __half2 h = __floats2half2_rn(a, b);
    return *reinterpret_cast<uint32_t*>(&h);
}

// D(16x8,f32) += A(16x16,f16 row) * B(16x8,f16 col)
__device__ __forceinline__ void mma16(float* c, const uint32_t* a,
                                      uint32_t b0, uint32_t b1) {
    asm volatile(
        "mma.sync.aligned.m16n8k16.row.col.f32.f16.f16.f32 "
        "{%0,%1,%2,%3},{%4,%5,%6,%7},{%8,%9},{%0,%1,%2,%3};\n"
        : "+f"(c[0]), "+f"(c[1]), "+f"(c[2]), "+f"(c[3])
        : "r"(a[0]), "r"(a[1]), "r"(a[2]), "r"(a[3]), "r"(b0), "r"(b1));
}

// ---------------------------------------------------------------------------
// Fused QKV projection: one launch. blockIdx.x selects {q,Wq,bq}/{k,..}/{v,..}
// C[M][1024] = X @ W^T + b, head-split write to g_Q/g_K/g_V.
// BM=BN=128, BK=16, fp16 smem, double-buffered, 8 warps (2x4), warp 64x32.
// ---------------------------------------------------------------------------
#define GKS 24   // smem k-stride (halves): 48B/row = 12-bank shift, conflict-free
#define GEMM_SMEM (4 * 128 * GKS * 2)   // 24,576 B

__global__ __launch_bounds__(256, 2)
void gemm_qkv(const float* __restrict__ xq, const float* __restrict__ xk,
              const float* __restrict__ xv,
              const float* __restrict__ Wq, const float* __restrict__ Wk,
              const float* __restrict__ Wv,
              const float* __restrict__ bq, const float* __restrict__ bk,
              const float* __restrict__ bv)
{
    extern __shared__ __half smh[];
    __half* Xb[2] = { smh,             smh + 2 * 128 * GKS };
    __half* Wb[2] = { smh + 128 * GKS, smh + 3 * 128 * GKS };

    const int sel = blockIdx.x >> 3;           // 0=Q 1=K 2=V
    const int n0  = (blockIdx.x & 7) * 128;
    const int m0  = blockIdx.y * 128;

    const float* X    = sel == 0 ? xq : sel == 1 ? xk : xv;
    const float* W    = sel == 0 ? Wq : sel == 1 ? Wk : Wv;
    const float* bias = sel == 0 ? bq : sel == 1 ? bk : bv;
    float* outp       = sel == 0 ? g_Q : sel == 1 ? g_K : g_V;

    const int t = threadIdx.x, lane = t & 31, w = t >> 5;
    const int g = lane >> 2, tg = lane & 3;
    const int wr = w >> 2, wc = w & 3;
    const int lr = t >> 1, lc = (t & 1) * 8;

    const float* Xrow = &X[(size_t)(m0 + lr) * D_MODEL + lc];
    const float* Wrow = &W[(size_t)(n0 + lr) * D_MODEL + lc];

    float acc[4][4][4];
    #pragma unroll
    for (int i = 0; i < 4; i++)
        #pragma unroll
        for (int j = 0; j < 4; j++)
            #pragma unroll
            for (int r = 0; r < 4; r++) acc[i][j][r] = 0.f;

    // prologue: stage k0=0
    {
        float4 x0 = *(const float4*)&Xrow[0];
        float4 x1 = *(const float4*)&Xrow[4];
        float4 w0 = *(const float4*)&Wrow[0];
        float4 w1 = *(const float4*)&Wrow[4];
        *(uint32_t*)&Xb[0][lr * GKS + lc]     = h2u(x0.x, x0.y);
        *(uint32_t*)&Xb[0][lr * GKS + lc + 2] = h2u(x0.z, x0.w);
        *(uint32_t*)&Xb[0][lr * GKS + lc + 4] = h2u(x1.x, x1.y);
        *(uint32_t*)&Xb[0][lr * GKS + lc + 6] = h2u(x1.z, x1.w);
        *(uint32_t*)&Wb[0][lr * GKS + lc]     = h2u(w0.x, w0.y);
        *(uint32_t*)&Wb[0][lr * GKS + lc + 2] = h2u(w0.z, w0.w);
        *(uint32_t*)&Wb[0][lr * GKS + lc + 4] = h2u(w1.x, w1.y);
        *(uint32_t*)&Wb[0][lr * GKS + lc + 6] = h2u(w1.z, w1.w);
    }
    __syncthreads();

    #pragma unroll 1
    for (int it = 0; it < 64; it++) {
        const __half* Xs = Xb[it & 1];
        const __half* Ws = Wb[it & 1];

        float4 x0, x1, w0, w1;
        const bool pre = (it < 63);
        if (pre) {
            const int k0 = (it + 1) * 16;
            x0 = *(const float4*)&Xrow[k0];
            x1 = *(const float4*)&Xrow[k0 + 4];
            w0 = *(const float4*)&Wrow[k0];
            w1 = *(const float4*)&Wrow[k0 + 4];
        }

        uint32_t a[4][4];
        #pragma unroll
        for (int i = 0; i < 4; i++) {
            const int base = wr * 64 + i * 16;
            a[i][0] = *(const uint32_t*)&Xs[(base + g)     * GKS + 2 * tg];
            a[i][1] = *(const uint32_t*)&Xs[(base + g + 8) * GKS + 2 * tg];
            a[i][2] = *(const uint32_t*)&Xs[(base + g)     * GKS + 2 * tg + 8];
            a[i][3] = *(const uint32_t*)&Xs[(base + g + 8) * GKS + 2 * tg + 8];
        }
        #pragma unroll
        for (int j = 0; j < 4; j++) {
            const int nb = wc * 32 + j * 8;
            uint32_t b0 = *(const uint32_t*)&Ws[(nb + g) * GKS + 2 * tg];
            uint32_t b1 = *(const uint32_t*)&Ws[(nb + g) * GKS + 2 * tg + 8];
            #pragma unroll
            for (int i = 0; i < 4; i++)
                mma16(acc[i][j], a[i], b0, b1);
        }

        if (pre) {
            __half* Xn = Xb[(it + 1) & 1];
            __half* Wn = Wb[(it + 1) & 1];
            *(uint32_t*)&Xn[lr * GKS + lc]     = h2u(x0.x, x0.y);
            *(uint32_t*)&Xn[lr * GKS + lc + 2] = h2u(x0.z, x0.w);
            *(uint32_t*)&Xn[lr * GKS + lc + 4] = h2u(x1.x, x1.y);
            *(uint32_t*)&Xn[lr * GKS + lc + 6] = h2u(x1.z, x1.w);
            *(uint32_t*)&Wn[lr * GKS + lc]     = h2u(w0.x, w0.y);
            *(uint32_t*)&Wn[lr * GKS + lc + 2] = h2u(w0.z, w0.w);
            *(uint32_t*)&Wn[lr * GKS + lc + 4] = h2u(w1.x, w1.y);
            *(uint32_t*)&Wn[lr * GKS + lc + 6] = h2u(w1.z, w1.w);
        }
        __syncthreads();
    }

    // epilogue: head-split write [B, H, S, Dh]
    #pragma unroll
    for (int j = 0; j < 4; j++) {
        const int colw = n0 + wc * 32 + j * 8 + 2 * tg;
        const float bz0 = bias[colw];
        const float bz1 = bias[colw + 1];
        const int hh = colw >> 6;
        const int dd = colw & (HEAD_DIM - 1);
        #pragma unroll
        for (int i = 0; i < 4; i++) {
            const int row0 = m0 + wr * 64 + i * 16 + g;
            const int row1 = row0 + 8;
            {
                const int b = row0 >> 11, s = row0 & (SEQ - 1);
                *(float2*)&outp[(((size_t)(b * N_HEADS + hh) * SEQ + s)) * HEAD_DIM + dd] =
                    make_float2(acc[i][j][0] + bz0, acc[i][j][1] + bz1);
            }
            {
                const int b = row1 >> 11, s = row1 & (SEQ - 1);
                *(float2*)&outp[(((size_t)(b * N_HEADS + hh) * SEQ + s)) * HEAD_DIM + dd] =
                    make_float2(acc[i][j][2] + bz0, acc[i][j][3] + bz1);
            }
        }
    }
}

// ---------------------------------------------------------------------------
// Output projection: out = ctx @ Wo^T + bo  (row-major write)
// ---------------------------------------------------------------------------
__global__ __launch_bounds__(256, 2)
void gemm_out(const float* __restrict__ Wo, const float* __restrict__ bo,
              float* __restrict__ outp)
{
    extern __shared__ __half smh[];
    __half* Xb[2] = { smh,             smh + 2 * 128 * GKS };
    __half* Wb[2] = { smh + 128 * GKS, smh + 3 * 128 * GKS };

    const int n0 = blockIdx.x * 128;
    const int m0 = blockIdx.y * 128;

    const int t = threadIdx.x, lane = t & 31, w = t >> 5;
    const int g = lane >> 2, tg = lane & 3;
    const int wr = w >> 2, wc = w & 3;
    const int lr = t >> 1, lc = (t & 1) * 8;

    const float* Xrow = &g_ctx[(size_t)(m0 + lr) * D_MODEL + lc];
    const float* Wrow = &Wo[(size_t)(n0 + lr) * D_MODEL + lc];

    float acc[4][4][4];
    #pragma unroll
    for (int i = 0; i < 4; i++)
        #pragma unroll
        for (int j = 0; j < 4; j++)
            #pragma unroll
            for (int r = 0; r < 4; r++) acc[i][j][r] = 0.f;

    {
        float4 x0 = *(const float4*)&Xrow[0];
        float4 x1 = *(const float4*)&Xrow[4];
        float4 w0 = *(const float4*)&Wrow[0];
        float4 w1 = *(const float4*)&Wrow[4];
        *(uint32_t*)&Xb[0][lr * GKS + lc]     = h2u(x0.x, x0.y);
        *(uint32_t*)&Xb[0][lr * GKS + lc + 2] = h2u(x0.z, x0.w);
        *(uint32_t*)&Xb[0][lr * GKS + lc + 4] = h2u(x1.x, x1.y);
        *(uint32_t*)&Xb[0][lr * GKS + lc + 6] = h2u(x1.z, x1.w);
        *(uint32_t*)&Wb[0][lr * GKS + lc]     = h2u(w0.x, w0.y);
        *(uint32_t*)&Wb[0][lr * GKS + lc + 2] = h2u(w0.z, w0.w);
        *(uint32_t*)&Wb[0][lr * GKS + lc + 4] = h2u(w1.x, w1.y);
        *(uint32_t*)&Wb[0][lr * GKS + lc + 6] = h2u(w1.z, w1.w);
    }
    __syncthreads();

    #pragma unroll 1
    for (int it = 0; it < 64; it++) {
        const __half* Xs = Xb[it & 1];
        const __half* Ws = Wb[it & 1];

        float4 x0, x1, w0, w1;
        const bool pre = (it < 63);
        if (pre) {
            const int k0 = (it + 1) * 16;
            x0 = *(const float4*)&Xrow[k0];
            x1 = *(const float4*)&Xrow[k0 + 4];
            w0 = *(const float4*)&Wrow[k0];
            w1 = *(const float4*)&Wrow[k0 + 4];
        }

        uint32_t a[4][4];
        #pragma unroll
        for (int i = 0; i < 4; i++) {
            const int base = wr * 64 + i * 16;
            a[i][0] = *(const uint32_t*)&Xs[(base + g)     * GKS + 2 * tg];
            a[i][1] = *(const uint32_t*)&Xs[(base + g + 8) * GKS + 2 * tg];
            a[i][2] = *(const uint32_t*)&Xs[(base + g)     * GKS + 2 * tg + 8];
            a[i][3] = *(const uint32_t*)&Xs[(base + g + 8) * GKS + 2 * tg + 8];
        }
        #pragma unroll
        for (int j = 0; j < 4; j++) {
            const int nb = wc * 32 + j * 8;
            uint32_t b0 = *(const uint32_t*)&Ws[(nb + g) * GKS + 2 * tg];
            uint32_t b1 = *(const uint32_t*)&Ws[(nb + g) * GKS + 2 * tg + 8];
            #pragma unroll
            for (int i = 0; i < 4; i++)
                mma16(acc[i][j], a[i], b0, b1);
        }

        if (pre) {
            __half* Xn = Xb[(it + 1) & 1];
            __half* Wn = Wb[(it + 1) & 1];
            *(uint32_t*)&Xn[lr * GKS + lc]     = h2u(x0.x, x0.y);
            *(uint32_t*)&Xn[lr * GKS + lc + 2] = h2u(x0.z, x0.w);
            *(uint32_t*)&Xn[lr * GKS + lc + 4] = h2u(x1.x, x1.y);
            *(uint32_t*)&Xn[lr * GKS + lc + 6] = h2u(x1.z, x1.w);
            *(uint32_t*)&Wn[lr * GKS + lc]     = h2u(w0.x, w0.y);
            *(uint32_t*)&Wn[lr * GKS + lc + 2] = h2u(w0.z, w0.w);
            *(uint32_t*)&Wn[lr * GKS + lc + 4] = h2u(w1.x, w1.y);
            *(uint32_t*)&Wn[lr * GKS + lc + 6] = h2u(w1.z, w1.w);
        }
        __syncthreads();
    }

    #pragma unroll
    for (int j = 0; j < 4; j++) {
        const int col = n0 + wc * 32 + j * 8 + 2 * tg;
        const float bz0 = bo[col];
        const float bz1 = bo[col + 1];
        #pragma unroll
        for (int i = 0; i < 4; i++) {
            const int row0 = m0 + wr * 64 + i * 16 + g;
            const int row1 = row0 + 8;
            *(float2*)&outp[(size_t)row0 * D_MODEL + col] =
                make_float2(acc[i][j][0] + bz0, acc[i][j][1] + bz1);
            *(float2*)&outp[(size_t)row1 * D_MODEL + col] =
                make_float2(acc[i][j][2] + bz0, acc[i][j][3] + bz1);
        }
    }
}

// ---------------------------------------------------------------------------
// Scores: S = SCALE * Q K^T (raw -> attn region) + per-tile softmax partials.
// fp16 mma, K=64 in one smem pass (4 k16 steps).
// ---------------------------------------------------------------------------
#define SSH 72
#define SCORES_SMEM (2 * 128 * SSH * 2)   // 36,864 B

__global__ __launch_bounds__(256, 2)
void scores_kernel(float* __restrict__ attnOut)
{
    const int n0 = blockIdx.x * 128;
    const int m0 = blockIdx.y * 128;
    const int bh = blockIdx.z;

    extern __shared__ __half smh[];
    __half* Qs = smh;
    __half* Ks = smh + 128 * SSH;

    const size_t hb = (size_t)bh * SEQ * HEAD_DIM;
    const float* Qg = g_Q + hb + (size_t)m0 * HEAD_DIM;
    const float* Kg = g_K + hb + (size_t)n0 * HEAD_DIM;

    const int t = threadIdx.x, lane = t & 31, w = t >> 5;
    const int g = lane >> 2, tg = lane & 3;
    const int wr = w >> 2, wc = w & 3;

    #pragma unroll
    for (int rep = 0; rep < 8; rep++) {
        const int idx = rep * 1024 + t * 4;
        const int r = idx >> 6, c = idx & 63;
        float4 qv = *(const float4*)&Qg[(size_t)r * HEAD_DIM + c];
        *(uint32_t*)&Qs[r * SSH + c]     = h2u(qv.x * SCALE_F, qv.y * SCALE_F);
        *(uint32_t*)&Qs[r * SSH + c + 2] = h2u(qv.z * SCALE_F, qv.w * SCALE_F);
        float4 kv = *(const float4*)&Kg[(size_t)r * HEAD_DIM + c];
        *(uint32_t*)&Ks[r * SSH + c]     = h2u(kv.x, kv.y);
        *(uint32_t*)&Ks[r * SSH + c + 2] = h2u(kv.z, kv.w);
    }
    __syncthreads();

    float acc[4][4][4];
    #pragma unroll
    for (int i = 0; i < 4; i++)
        #pragma unroll
        for (int j = 0; j < 4; j++)
            #pragma unroll
            for (int r = 0; r < 4; r++) acc[i][j][r] = 0.f;

    #pragma unroll
    for (int kk = 0; kk < 4; kk++) {
        const int kb = kk * 16;
        uint32_t a[4][4];
        #pragma unroll
        for (int i = 0; i < 4; i++) {
            const int base = wr * 64 + i * 16;
            a[i][0] = *(const uint32_t*)&Qs[(base + g)     * SSH + kb + 2 * tg];
            a[i][1] = *(const uint32_t*)&Qs[(base + g + 8) * SSH + kb + 2 * tg];
            a[i][2] = *(const uint32_t*)&Qs[(base + g)     * SSH + kb + 2 * tg + 8];
            a[i][3] = *(const uint32_t*)&Qs[(base + g + 8) * SSH + kb + 2 * tg + 8];
        }
        #pragma unroll
        for (int j = 0; j < 4; j++) {
            const int nb = wc * 32 + j * 8;
            uint32_t b0 = *(const uint32_t*)&Ks[(nb + g) * SSH + kb + 2 * tg];
            uint32_t b1 = *(const uint32_t*)&Ks[(nb + g) * SSH + kb + 2 * tg + 8];
            #pragma unroll
            for (int i = 0; i < 4; i++)
                mma16(acc[i][j], a[i], b0, b1);
        }
    }

    // write raw scores
    float* Sout = attnOut + (size_t)bh * SEQ * SEQ;
    #pragma unroll
    for (int j = 0; j < 4; j++) {
        const int col = n0 + wc * 32 + j * 8 + 2 * tg;
        #pragma unroll
        for (int i = 0; i < 4; i++) {
            const int row0 = m0 + wr * 64 + i * 16 + g;
            *(float2*)&Sout[(size_t)row0 * SEQ + col] =
                make_float2(acc[i][j][0], acc[i][j][1]);
            *(float2*)&Sout[(size_t)(row0 + 8) * SEQ + col] =
                make_float2(acc[i][j][2], acc[i][j][3]);
        }
    }

    // ---- softmax partials from registers ----
    __syncthreads();
    float* stmax = (float*)smh;          // [128][4]
    float* stsum = (float*)smh + 512;    // [128][4]

    #pragma unroll
    for (int i = 0; i < 4; i++) {
        float m0v = -1e30f, m1v = -1e30f;
        #pragma unroll
        for (int j = 0; j < 4; j++) {
            m0v = fmaxf(m0v, fmaxf(acc[i][j][0], acc[i][j][1]));
            m1v = fmaxf(m1v, fmaxf(acc[i][j][2], acc[i][j][3]));
        }
        m0v = fmaxf(m0v, __shfl_xor_sync(0xFFFFFFFFu, m0v, 1));
        m0v = fmaxf(m0v, __shfl_xor_sync(0xFFFFFFFFu, m0v, 2));
        m1v = fmaxf(m1v, __shfl_xor_sync(0xFFFFFFFFu, m1v, 1));
        m1v = fmaxf(m1v, __shfl_xor_sync(0xFFFFFFFFu, m1v, 2));
        if (tg == 0) {
            const int r0 = wr * 64 + i * 16 + g;
            stmax[r0 * 4 + wc]       = m0v;
            stmax[(r0 + 8) * 4 + wc] = m1v;
        }
    }
    __syncthreads();

    #pragma unroll
    for (int i = 0; i < 4; i++) {
        const int r0 = wr * 64 + i * 16 + g;
        const float M0 = fmaxf(fmaxf(stmax[r0 * 4 + 0], stmax[r0 * 4 + 1]),
                               fmaxf(stmax[r0 * 4 + 2], stmax[r0 * 4 + 3]));
        const int r1 = r0 + 8;
        const float M1 = fmaxf(fmaxf(stmax[r1 * 4 + 0], stmax[r1 * 4 + 1]),
                               fmaxf(stmax[r1 * 4 + 2], stmax[r1 * 4 + 3]));
        float s0 = 0.f, s1 = 0.f;
        #pragma unroll
        for (int j = 0; j < 4; j++) {
            s0 += __expf(acc[i][j][0] - M0) + __expf(acc[i][j][1] - M0);
            s1 += __expf(acc[i][j][2] - M1) + __expf(acc[i][j][3] - M1);
        }
        s0 += __shfl_xor_sync(0xFFFFFFFFu, s0, 1);
        s0 += __shfl_xor_sync(0xFFFFFFFFu, s0, 2);
        s1 += __shfl_xor_sync(0xFFFFFFFFu, s1, 1);
        s1 += __shfl_xor_sync(0xFFFFFFFFu, s1, 2);
        if (tg == 0) {
            stsum[r0 * 4 + wc] = s0;
            stsum[r1 * 4 + wc] = s1;
        }
    }
    __syncthreads();

    if (t < 128) {
        const float M = fmaxf(fmaxf(stmax[t * 4 + 0], stmax[t * 4 + 1]),
                              fmaxf(stmax[t * 4 + 2], stmax[t * 4 + 3]));
        const float S = stsum[t * 4 + 0] + stsum[t * 4 + 1] +
                        stsum[t * 4 + 2] + stsum[t * 4 + 3];
        const size_t p = ((size_t)bh * SEQ + m0 + t) * NTILES + blockIdx.x;
        g_pmax[p] = M;
        g_psum[p] = S;
    }
}

// ---------------------------------------------------------------------------
// PV: combines partials in prologue, applies softmax inline (write attn back
// in place), ctx = P @ V via fp16 mma. V staged transposed for half2 B-frags.
// ---------------------------------------------------------------------------
#define PSH 136
#define VSH 136
#define PV_SMEM (1024 + 128 * PSH * 2 + 64 * VSH * 2)   // 53,248 B

__global__ __launch_bounds__(256, 2)
void pv_kernel(float* __restrict__ attnOut)
{
    const int m0 = blockIdx.x * 128;
    const int bh = blockIdx.y;
    const int bb = bh >> 4, hh = bh & 15;

    extern __shared__ char smc[];
    float2* rs  = (float2*)smc;                 // [128] (rowmax, 1/rowsum)
    __half* Ps  = (__half*)(smc + 1024);        // [128][PSH]
    __half* VsT = Ps + 128 * PSH;               // [64][VSH]

    float* Pg = attnOut + (size_t)bh * SEQ * SEQ + (size_t)m0 * SEQ;
    const float* Vg = g_V + (size_t)bh * SEQ * HEAD_DIM;

    const int t = threadIdx.x, lane = t & 31, w = t >> 5;
    const int g = lane >> 2, tg = lane & 3;

    // prologue: fold softmax partials for this block's 128 rows
    if (t < 128) {
        const float* pm = &g_pmax[((size_t)bh * SEQ + m0 + t) * NTILES];
        const float* ps = &g_psum[((size_t)bh * SEQ + m0 + t) * NTILES];
        float m[NTILES], s[NTILES];
        #pragma unroll
        for (int i = 0; i < NTILES; i += 4) {
            float4 a = *(const float4*)&pm[i];
            m[i] = a.x; m[i+1] = a.y; m[i+2] = a.z; m[i+3] = a.w;
            float4 b = *(const float4*)&ps[i];
            s[i] = b.x; s[i+1] = b.y; s[i+2] = b.z; s[i+3] = b.w;
        }
        float M = m[0];
        #pragma unroll
        for (int i = 1; i < NTILES; i++) M = fmaxf(M, m[i]);
        float l = 0.f;
        #pragma unroll
        for (int i = 0; i < NTILES; i++) l += s[i] * __expf(m[i] - M);
        rs[t] = make_float2(M, 1.f / l);
    }
    __syncthreads();

    float acc[8][4];
    #pragma unroll
    for (int j = 0; j < 8; j++)
        #pragma unroll
        for (int r = 0; r < 4; r++) acc[j][r] = 0.f;

    for (int k0 = 0; k0 < SEQ; k0 += 128) {
        __syncthreads();
        // P tile: exp-normalize, write attn back, stage fp16
        #pragma unroll
        for (int rep = 0; rep < 16; rep++) {
            const int idx = rep * 1024 + t * 4;
            const int r = idx >> 7, c = idx & 127;
            const float2 st = rs[r];
            float4 p = *(const float4*)&Pg[(size_t)r * SEQ + k0 + c];
            p.x = __expf(p.x - st.x) * st.y;
            p.y = __expf(p.y - st.x) * st.y;
            p.z = __expf(p.z - st.x) * st.y;
            p.w = __expf(p.w - st.x) * st.y;
            *(float4*)&Pg[(size_t)r * SEQ + k0 + c] = p;
            *(uint32_t*)&Ps[r * PSH + c]     = h2u(p.x, p.y);
            *(uint32_t*)&Ps[r * PSH + c + 2] = h2u(p.z, p.w);
        }
        // V tile transposed: VsT[n][k]
        #pragma unroll
        for (int rep = 0; rep < 8; rep++) {
            const int idx = rep * 1024 + t * 4;
            const int r = idx >> 6, c = idx & 63;
            float4 vv = *(const float4*)&Vg[(size_t)(k0 + r) * HEAD_DIM + c];
            VsT[(c + 0) * VSH + r] = __float2half_rn(vv.x);
            VsT[(c + 1) * VSH + r] = __float2half_rn(vv.y);
            VsT[(c + 2) * VSH + r] = __float2half_rn(vv.z);
            VsT[(c + 3) * VSH + r] = __float2half_rn(vv.w);
        }
        __syncthreads();

        #pragma unroll
        for (int kk = 0; kk < 8; kk++) {
            const int kb = kk * 16;
            const int pr = (w * 16 + g) * PSH + kb + 2 * tg;
            uint32_t a[4];
            a[0] = *(const uint32_t*)&Ps[pr];
            a[1] = *(const uint32_t*)&Ps[pr + 8 * PSH];
            a[2] = *(const uint32_t*)&Ps[pr + 8];
            a[3] = *(const uint32_t*)&Ps[pr + 8 * PSH + 8];
            #pragma unroll
            for (int j = 0; j < 8; j++) {
                const int nb = j * 8;
                uint32_t b0 = *(const uint32_t*)&VsT[(nb + g) * VSH + kb + 2 * tg];
                uint32_t b1 = *(const uint32_t*)&VsT[(nb + g) * VSH + kb + 2 * tg + 8];
                mma16(acc[j], a, b0, b1);
            }
        }
    }

    #pragma unroll
    for (int j = 0; j < 8; j++) {
        const int col = hh * HEAD_DIM + j * 8 + 2 * tg;
        const int row0 = m0 + w * 16 + g;
        const int row1 = row0 + 8;
        *(float2*)&g_ctx[(size_t)(bb * SEQ + row0) * D_MODEL + col] =
            make_float2(acc[j][0], acc[j][1]);
        *(float2*)&g_ctx[(size_t)(bb * SEQ + row1) * D_MODEL + col] =
            make_float2(acc[j][2], acc[j][3]);
    }
}

// ---------------------------------------------------------------------------
extern "C" void kernel_launch(void* const* d_in, const int* in_sizes, int n_in,
                              void* d_out, int out_size)
{
    const float* q  = (const float*)d_in[0];
    const float* k  = (const float*)d_in[1];
    const float* v  = (const float*)d_in[2];
    const float* Wq = (const float*)d_in[3];
    const float* bq = (const float*)d_in[4];
    const float* Wk = (const float*)d_in[5];
    const float* bk = (const float*)d_in[6];
    const float* Wv = (const float*)d_in[7];
    const float* bv = (const float*)d_in[8];
    const float* Wo = (const float*)d_in[9];
    const float* bo = (const float*)d_in[10];
    float* out  = (float*)d_out;
    float* attn = out + OUT_ELEMS;

    cudaFuncSetAttribute(pv_kernel,
                         cudaFuncAttributeMaxDynamicSharedMemorySize, PV_SMEM);

    gemm_qkv<<<dim3(24, M_ROWS / 128), 256, GEMM_SMEM>>>(
        q, k, v, Wq, Wk, Wv, bq, bk, bv);

    scores_kernel<<<dim3(NTILES, NTILES, NBH), 256, SCORES_SMEM>>>(attn);
    pv_kernel<<<dim3(NTILES, NBH), 256, PV_SMEM>>>(attn);

    gemm_out<<<dim3(D_MODEL / 128, M_ROWS / 128), 256, GEMM_SMEM>>>(Wo, bo, out);
}

// round 6
// speedup vs baseline: 4.4134x; 1.0200x over previous
#include <cuda_runtime.h>
#include <cuda_fp16.h>
#include <stdint.h>

// Problem constants
#define D_MODEL   1024
#define N_HEADS   16
#define HEAD_DIM  64
#define BATCH     2
#define SEQ       2048
#define M_ROWS    4096
#define OUT_ELEMS ((size_t)M_ROWS * D_MODEL)
#define SCALE_F   0.125f
#define NBH       32
#define NTILES    16

// fp16 scratch (device globals; no allocation allowed)
__device__ __half g_qh[M_ROWS * D_MODEL];
__device__ __half g_kh[M_ROWS * D_MODEL];
__device__ __half g_vh[M_ROWS * D_MODEL];
__device__ __half g_Wqh[D_MODEL * D_MODEL];
__device__ __half g_Wkh[D_MODEL * D_MODEL];
__device__ __half g_Wvh[D_MODEL * D_MODEL];
__device__ __half g_Woh[D_MODEL * D_MODEL];
__device__ __half g_Qh[NBH * SEQ * HEAD_DIM];   // pre-scaled by SCALE_F
__device__ __half g_Kh[NBH * SEQ * HEAD_DIM];
__device__ __half g_Vh[NBH * SEQ * HEAD_DIM];
__device__ __half g_ctxh[M_ROWS * D_MODEL];

// ---------------------------------------------------------------------------
// helpers
// ---------------------------------------------------------------------------
__device__ __forceinline__ uint32_t h2u(float a, float b) {
    __half2 h = __floats2half2_rn(a, b);
    return *reinterpret_cast<uint32_t*>(&h);
}

__device__ __forceinline__ void mma16(float* c, const uint32_t* a,
                                      uint32_t b0, uint32_t b1) {
    asm volatile(
        "mma.sync.aligned.m16n8k16.row.col.f32.f16.f16.f32 "
        "{%0,%1,%2,%3},{%4,%5,%6,%7},{%8,%9},{%0,%1,%2,%3};\n"
        : "+f"(c[0]), "+f"(c[1]), "+f"(c[2]), "+f"(c[3])
        : "r"(a[0]), "r"(a[1]), "r"(a[2]), "r"(a[3]), "r"(b0), "r"(b1));
}

__device__ __forceinline__ void cp16(uint32_t dst, const void* src) {
    asm volatile("cp.async.ca.shared.global [%0], [%1], 16;\n"
                 :: "r"(dst), "l"(src));
}
#define CP_COMMIT() asm volatile("cp.async.commit_group;\n" ::)
#define CP_WAIT2()  asm volatile("cp.async.wait_group 2;\n" ::)
#define CP_WAIT0()  asm volatile("cp.async.wait_group 0;\n" ::)

// ---------------------------------------------------------------------------
// Convert fp32 -> fp16 (7 segments: q, k, v, Wq, Wk, Wv, Wo)
// ---------------------------------------------------------------------------
__global__ __launch_bounds__(256)
void convert_all(const float* __restrict__ q, const float* __restrict__ k,
                 const float* __restrict__ v, const float* __restrict__ Wq,
                 const float* __restrict__ Wk, const float* __restrict__ Wv,
                 const float* __restrict__ Wo)
{
    const int seg = blockIdx.y;
    const float* src; __half* dst; int n;
    switch (seg) {
        case 0: src = q;  dst = g_qh;  n = M_ROWS * D_MODEL; break;
        case 1: src = k;  dst = g_kh;  n = M_ROWS * D_MODEL; break;
        case 2: src = v;  dst = g_vh;  n = M_ROWS * D_MODEL; break;
        case 3: src = Wq; dst = g_Wqh; n = D_MODEL * D_MODEL; break;
        case 4: src = Wk; dst = g_Wkh; n = D_MODEL * D_MODEL; break;
        case 5: src = Wv; dst = g_Wvh; n = D_MODEL * D_MODEL; break;
        default: src = Wo; dst = g_Woh; n = D_MODEL * D_MODEL; break;
    }
    const int idx = (blockIdx.x * 256 + threadIdx.x) * 8;
    if (idx >= n) return;
    float4 a = *(const float4*)&src[idx];
    float4 b = *(const float4*)&src[idx + 4];
    uint4 o;
    o.x = h2u(a.x, a.y); o.y = h2u(a.z, a.w);
    o.z = h2u(b.x, b.y); o.w = h2u(b.z, b.w);
    *(uint4*)&dst[idx] = o;
}

// ---------------------------------------------------------------------------
// GEMM core: BM=BN=128, BK=16, fp16 cp.async 4-stage pipeline, 8 warps (2x4)
// ---------------------------------------------------------------------------
#define GKS 24                       // smem row stride (halves)
#define GSTAGE (128 * GKS)           // halves per matrix per stage
#define GEMM_SMEM (4 * 2 * GSTAGE * 2)   // 49,152 B

// QKV projection (one launch, sel = blockIdx.x>>3). Writes fp16 head-split.
__global__ __launch_bounds__(256, 2)
void gemm_qkv(const float* __restrict__ bq, const float* __restrict__ bk,
              const float* __restrict__ bv)
{
    extern __shared__ __half smh[];
    const int sel = blockIdx.x >> 3;
    const int n0  = (blockIdx.x & 7) * 128;
    const int m0  = blockIdx.y * 128;

    const __half* X = sel == 0 ? g_qh : sel == 1 ? g_kh : g_vh;
    const __half* W = sel == 0 ? g_Wqh : sel == 1 ? g_Wkh : g_Wvh;
    const float* bias = sel == 0 ? bq : sel == 1 ? bk : bv;
    __half* outp = sel == 0 ? g_Qh : sel == 1 ? g_Kh : g_Vh;
    const float oscale = sel == 0 ? SCALE_F : 1.f;

    const int t = threadIdx.x, lane = t & 31, w = t >> 5;
    const int g = lane >> 2, tg = lane & 3;
    const int wr = w >> 2, wc = w & 3;
    const int lr = t >> 1, lc = (t & 1) * 8;

    const __half* Xsrc = X + (size_t)(m0 + lr) * D_MODEL + lc;
    const __half* Wsrc = W + (size_t)(n0 + lr) * D_MODEL + lc;
    const uint32_t sbase = (uint32_t)__cvta_generic_to_shared(smh);
    const uint32_t xdst0 = sbase + (lr * GKS + lc) * 2;
    const uint32_t wdst0 = xdst0 + GSTAGE * 2;

    float acc[4][4][4] = {};

    #pragma unroll
    for (int s = 0; s < 3; s++) {
        cp16(xdst0 + s * 2 * GSTAGE * 2, Xsrc + s * 16);
        cp16(wdst0 + s * 2 * GSTAGE * 2, Wsrc + s * 16);
        CP_COMMIT();
    }

    #pragma unroll 1
    for (int it = 0; it < 64; it++) {
        CP_WAIT2();
        __syncthreads();
        if (it + 3 < 64) {
            const int s = (it + 3) & 3;
            cp16(xdst0 + s * 2 * GSTAGE * 2, Xsrc + (it + 3) * 16);
            cp16(wdst0 + s * 2 * GSTAGE * 2, Wsrc + (it + 3) * 16);
        }
        CP_COMMIT();

        const __half* Xs = smh + (it & 3) * 2 * GSTAGE;
        const __half* Ws = Xs + GSTAGE;

        uint32_t a[4][4];
        #pragma unroll
        for (int i = 0; i < 4; i++) {
            const int base = wr * 64 + i * 16;
            a[i][0] = *(const uint32_t*)&Xs[(base + g)     * GKS + 2 * tg];
            a[i][1] = *(const uint32_t*)&Xs[(base + g + 8) * GKS + 2 * tg];
            a[i][2] = *(const uint32_t*)&Xs[(base + g)     * GKS + 2 * tg + 8];
            a[i][3] = *(const uint32_t*)&Xs[(base + g + 8) * GKS + 2 * tg + 8];
        }
        #pragma unroll
        for (int j = 0; j < 4; j++) {
            const int nb = wc * 32 + j * 8;
            uint32_t b0 = *(const uint32_t*)&Ws[(nb + g) * GKS + 2 * tg];
            uint32_t b1 = *(const uint32_t*)&Ws[(nb + g) * GKS + 2 * tg + 8];
            #pragma unroll
            for (int i = 0; i < 4; i++)
                mma16(acc[i][j], a[i], b0, b1);
        }
    }

    // epilogue: fp16 head-split write [B, H, S, Dh] (Q pre-scaled)
    #pragma unroll
    for (int j = 0; j < 4; j++) {
        const int colw = n0 + wc * 32 + j * 8 + 2 * tg;
        const float bz0 = bias[colw];
        const float bz1 = bias[colw + 1];
        const int hh = colw >> 6;
        const int dd = colw & (HEAD_DIM - 1);
        #pragma unroll
        for (int i = 0; i < 4; i++) {
            const int row0 = m0 + wr * 64 + i * 16 + g;
            const int row1 = row0 + 8;
            {
                const int b = row0 >> 11, s = row0 & (SEQ - 1);
                *(__half2*)&outp[(((size_t)(b * N_HEADS + hh) * SEQ + s)) * HEAD_DIM + dd] =
                    __floats2half2_rn((acc[i][j][0] + bz0) * oscale,
                                      (acc[i][j][1] + bz1) * oscale);
            }
            {
                const int b = row1 >> 11, s = row1 & (SEQ - 1);
                *(__half2*)&outp[(((size_t)(b * N_HEADS + hh) * SEQ + s)) * HEAD_DIM + dd] =
                    __floats2half2_rn((acc[i][j][2] + bz0) * oscale,
                                      (acc[i][j][3] + bz1) * oscale);
            }
        }
    }
}

// Output projection: out = ctx(fp16) @ Wo^T + bo, fp32 row-major write.
__global__ __launch_bounds__(256, 2)
void gemm_out(const float* __restrict__ bo, float* __restrict__ outp)
{
    extern __shared__ __half smh[];
    const int n0 = blockIdx.x * 128;
    const int m0 = blockIdx.y * 128;

    const int t = threadIdx.x, lane = t & 31, w = t >> 5;
    const int g = lane >> 2, tg = lane & 3;
    const int wr = w >> 2, wc = w & 3;
    const int lr = t >> 1, lc = (t & 1) * 8;

    const __half* Xsrc = g_ctxh + (size_t)(m0 + lr) * D_MODEL + lc;
    const __half* Wsrc = g_Woh + (size_t)(n0 + lr) * D_MODEL + lc;
    const uint32_t sbase = (uint32_t)__cvta_generic_to_shared(smh);
    const uint32_t xdst0 = sbase + (lr * GKS + lc) * 2;
    const uint32_t wdst0 = xdst0 + GSTAGE * 2;

    float acc[4][4][4] = {};

    #pragma unroll
    for (int s = 0; s < 3; s++) {
        cp16(xdst0 + s * 2 * GSTAGE * 2, Xsrc + s * 16);
        cp16(wdst0 + s * 2 * GSTAGE * 2, Wsrc + s * 16);
        CP_COMMIT();
    }

    #pragma unroll 1
    for (int it = 0; it < 64; it++) {
        CP_WAIT2();
        __syncthreads();
        if (it + 3 < 64) {
            const int s = (it + 3) & 3;
            cp16(xdst0 + s * 2 * GSTAGE * 2, Xsrc + (it + 3) * 16);
            cp16(wdst0 + s * 2 * GSTAGE * 2, Wsrc + (it + 3) * 16);
        }
        CP_COMMIT();

        const __half* Xs = smh + (it & 3) * 2 * GSTAGE;
        const __half* Ws = Xs + GSTAGE;

        uint32_t a[4][4];
        #pragma unroll
        for (int i = 0; i < 4; i++) {
            const int base = wr * 64 + i * 16;
            a[i][0] = *(const uint32_t*)&Xs[(base + g)     * GKS + 2 * tg];
            a[i][1] = *(const uint32_t*)&Xs[(base + g + 8) * GKS + 2 * tg];
            a[i][2] = *(const uint32_t*)&Xs[(base + g)     * GKS + 2 * tg + 8];
            a[i][3] = *(const uint32_t*)&Xs[(base + g + 8) * GKS + 2 * tg + 8];
        }
        #pragma unroll
        for (int j = 0; j < 4; j++) {
            const int nb = wc * 32 + j * 8;
            uint32_t b0 = *(const uint32_t*)&Ws[(nb + g) * GKS + 2 * tg];
            uint32_t b1 = *(const uint32_t*)&Ws[(nb + g) * GKS + 2 * tg + 8];
            #pragma unroll
            for (int i = 0; i < 4; i++)
                mma16(acc[i][j], a[i], b0, b1);
        }
    }

    #pragma unroll
    for (int j = 0; j < 4; j++) {
        const int col = n0 + wc * 32 + j * 8 + 2 * tg;
        const float bz0 = bo[col];
        const float bz1 = bo[col + 1];
        #pragma unroll
        for (int i = 0; i < 4; i++) {
            const int row0 = m0 + wr * 64 + i * 16 + g;
            const int row1 = row0 + 8;
            *(float2*)&outp[(size_t)row0 * D_MODEL + col] =
                make_float2(acc[i][j][0] + bz0, acc[i][j][1] + bz1);
            *(float2*)&outp[(size_t)row1 * D_MODEL + col] =
                make_float2(acc[i][j][2] + bz0, acc[i][j][3] + bz1);
        }
    }
}

// ---------------------------------------------------------------------------
// Fused attention: per (bh, 128-row m-tile).
// Phase A: stream K tiles, S=Q K^T via mma, online per-thread (max, sumexp).
// Phase B: recompute S, p = exp(s-M)/L, write attn once, O += p V.
// ---------------------------------------------------------------------------
#define QKS  72
#define VSH2 136
#define PSH2 136
#define ATT_SMEM (1024 + 2 * 128 * QKS * 2 + 64 * VSH2 * 2 + 128 * PSH2 * 2) // 90,112

__global__ __launch_bounds__(256, 2)
void attn_fused(float* __restrict__ attnOut)
{
    const int m0 = blockIdx.x * 128;
    const int bh = blockIdx.y;
    const int bb = bh >> 4, hh = bh & 15;

    extern __shared__ char smc[];
    float2* rs  = (float2*)smc;                       // [128] (M, 1/L)
    __half* Qs  = (__half*)(smc + 1024);              // [128][QKS]
    __half* Ks  = Qs + 128 * QKS;                     // [128][QKS]
    __half* VsT = Ks + 128 * QKS;                     // [64][VSH2]
    __half* Ps  = VsT + 64 * VSH2;                    // [128][PSH2]

    const __half* Qg = g_Qh + ((size_t)bh * SEQ + m0) * HEAD_DIM;
    const __half* Kg = g_Kh + (size_t)bh * SEQ * HEAD_DIM;
    const __half* Vg = g_Vh + (size_t)bh * SEQ * HEAD_DIM;
    float* attnP = attnOut + (size_t)bh * SEQ * SEQ + (size_t)m0 * SEQ;

    const int t = threadIdx.x, lane = t & 31, w = t >> 5;
    const int g = lane >> 2, tg = lane & 3;
    const int wr = w >> 2, wc = w & 3;

    const uint32_t qsb = (uint32_t)__cvta_generic_to_shared(Qs);
    const uint32_t ksb = (uint32_t)__cvta_generic_to_shared(Ks);

    // stage Q once (fp16, pre-scaled)
    #pragma unroll
    for (int rep = 0; rep < 4; rep++) {
        const int c = rep * 256 + t;
        const int r = c >> 3, o = (c & 7) * 8;
        cp16(qsb + (r * QKS + o) * 2, Qg + (size_t)r * HEAD_DIM + o);
    }
    CP_COMMIT();

    // ---- Phase A: online row stats ----
    float mrun[8], lrun[8];
    #pragma unroll
    for (int s = 0; s < 8; s++) { mrun[s] = -1e30f; lrun[s] = 0.f; }

    #pragma unroll 1
    for (int kt = 0; kt < NTILES; kt++) {
        __syncthreads();   // previous tile's Ks reads done
        #pragma unroll
        for (int rep = 0; rep < 4; rep++) {
            const int c = rep * 256 + t;
            const int r = c >> 3, o = (c & 7) * 8;
            cp16(ksb + (r * QKS + o) * 2, Kg + (size_t)(kt * 128 + r) * HEAD_DIM + o);
        }
        CP_COMMIT();
        CP_WAIT0();
        __syncthreads();

        #pragma unroll
        for (int h = 0; h < 2; h++) {
            float acc[4][2][4] = {};
            #pragma unroll
            for (int kk = 0; kk < 4; kk++) {
                const int kb = kk * 16;
                uint32_t a[4][4];
                #pragma unroll
                for (int i = 0; i < 4; i++) {
                    const int base = wr * 64 + i * 16;
                    a[i][0] = *(const uint32_t*)&Qs[(base + g)     * QKS + kb + 2 * tg];
                    a[i][1] = *(const uint32_t*)&Qs[(base + g + 8) * QKS + kb + 2 * tg];
                    a[i][2] = *(const uint32_t*)&Qs[(base + g)     * QKS + kb + 2 * tg + 8];
                    a[i][3] = *(const uint32_t*)&Qs[(base + g + 8) * QKS + kb + 2 * tg + 8];
                }
                #pragma unroll
                for (int j = 0; j < 2; j++) {
                    const int nb = h * 64 + wc * 16 + j * 8;
                    uint32_t b0 = *(const uint32_t*)&Ks[(nb + g) * QKS + kb + 2 * tg];
                    uint32_t b1 = *(const uint32_t*)&Ks[(nb + g) * QKS + kb + 2 * tg + 8];
                    #pragma unroll
                    for (int i = 0; i < 4; i++)
                        mma16(acc[i][j], a[i], b0, b1);
                }
            }
            // online update
            #pragma unroll
            for (int i = 0; i < 4; i++) {
                #pragma unroll
                for (int half = 0; half < 2; half++) {
                    const int s = i * 2 + half;
                    const float v0 = acc[i][0][half * 2];
                    const float v1 = acc[i][0][half * 2 + 1];
                    const float v2 = acc[i][1][half * 2];
                    const float v3 = acc[i][1][half * 2 + 1];
                    const float tm = fmaxf(fmaxf(v0, v1), fmaxf(v2, v3));
                    const float m2 = fmaxf(mrun[s], tm);
                    lrun[s] = lrun[s] * __expf(mrun[s] - m2)
                            + __expf(v0 - m2) + __expf(v1 - m2)
                            + __expf(v2 - m2) + __expf(v3 - m2);
                    mrun[s] = m2;
                }
            }
        }
    }

    // reduce (m,l) across tg, then across wc via smem
    #pragma unroll
    for (int s = 0; s < 8; s++) {
        #pragma unroll
        for (int off = 1; off <= 2; off <<= 1) {
            const float mo = __shfl_xor_sync(0xFFFFFFFFu, mrun[s], off);
            const float lo = __shfl_xor_sync(0xFFFFFFFFu, lrun[s], off);
            const float m2 = fmaxf(mrun[s], mo);
            lrun[s] = lrun[s] * __expf(mrun[s] - m2) + lo * __expf(mo - m2);
            mrun[s] = m2;
        }
    }
    __syncthreads();
    {
        float* stm = (float*)Ps;         // [128][4]
        float* stl = stm + 512;
        if (tg == 0) {
            #pragma unroll
            for (int s = 0; s < 8; s++) {
                const int i = s >> 1, half = s & 1;
                const int row = wr * 64 + i * 16 + half * 8 + g;
                stm[row * 4 + wc] = mrun[s];
                stl[row * 4 + wc] = lrun[s];
            }
        }
        __syncthreads();
        if (t < 128) {
            float M = stm[t * 4];
            #pragma unroll
            for (int c = 1; c < 4; c++) M = fmaxf(M, stm[t * 4 + c]);
            float L = 0.f;
            #pragma unroll
            for (int c = 0; c < 4; c++)
                L += stl[t * 4 + c] * __expf(stm[t * 4 + c] - M);
            rs[t] = make_float2(M, 1.f / L);
        }
        __syncthreads();
    }

    // ---- Phase B: recompute S, write attn, accumulate O ----
    float oacc[8][4] = {};

    #pragma unroll 1
    for (int kt = 0; kt < NTILES; kt++) {
        __syncthreads();   // protect Ks/VsT/Ps from previous readers
        #pragma unroll
        for (int rep = 0; rep < 4; rep++) {
            const int c = rep * 256 + t;
            const int r = c >> 3, o = (c & 7) * 8;
            cp16(ksb + (r * QKS + o) * 2, Kg + (size_t)(kt * 128 + r) * HEAD_DIM + o);
        }
        CP_COMMIT();
        // V tile scatter-transpose: VsT[d][k]
        #pragma unroll
        for (int rep = 0; rep < 4; rep++) {
            const int c = rep * 256 + t;
            const int r = c >> 3, o = (c & 7) * 8;
            uint4 vv = *(const uint4*)&Vg[(size_t)(kt * 128 + r) * HEAD_DIM + o];
            const __half* hv = (const __half*)&vv;
            #pragma unroll
            for (int i = 0; i < 8; i++)
                VsT[(o + i) * VSH2 + r] = hv[i];
        }
        CP_WAIT0();
        __syncthreads();

        #pragma unroll
        for (int h = 0; h < 2; h++) {
            float acc[4][2][4] = {};
            #pragma unroll
            for (int kk = 0; kk < 4; kk++) {
                const int kb = kk * 16;
                uint32_t a[4][4];
                #pragma unroll
                for (int i = 0; i < 4; i++) {
                    const int base = wr * 64 + i * 16;
                    a[i][0] = *(const uint32_t*)&Qs[(base + g)     * QKS + kb + 2 * tg];
                    a[i][1] = *(const uint32_t*)&Qs[(base + g + 8) * QKS + kb + 2 * tg];
                    a[i][2] = *(const uint32_t*)&Qs[(base + g)     * QKS + kb + 2 * tg + 8];
                    a[i][3] = *(const uint32_t*)&Qs[(base + g + 8) * QKS + kb + 2 * tg + 8];
                }
                #pragma unroll
                for (int j = 0; j < 2; j++) {
                    const int nb = h * 64 + wc * 16 + j * 8;
                    uint32_t b0 = *(const uint32_t*)&Ks[(nb + g) * QKS + kb + 2 * tg];
                    uint32_t b1 = *(const uint32_t*)&Ks[(nb + g) * QKS + kb + 2 * tg + 8];
                    #pragma unroll
                    for (int i = 0; i < 4; i++)
                        mma16(acc[i][j], a[i], b0, b1);
                }
            }
            // normalize, write attn (final), stage fp16 P
            #pragma unroll
            for (int i = 0; i < 4; i++) {
                const int row0 = wr * 64 + i * 16 + g;
                const int row1 = row0 + 8;
                const float2 st0 = rs[row0];
                const float2 st1 = rs[row1];
                #pragma unroll
                for (int j = 0; j < 2; j++) {
                    const int col = h * 64 + wc * 16 + j * 8 + 2 * tg;
                    const float p0 = __expf(acc[i][j][0] - st0.x) * st0.y;
                    const float p1 = __expf(acc[i][j][1] - st0.x) * st0.y;
                    const float p2 = __expf(acc[i][j][2] - st1.x) * st1.y;
                    const float p3 = __expf(acc[i][j][3] - st1.x) * st1.y;
                    *(float2*)&attnP[(size_t)row0 * SEQ + kt * 128 + col] =
                        make_float2(p0, p1);
                    *(float2*)&attnP[(size_t)row1 * SEQ + kt * 128 + col] =
                        make_float2(p2, p3);
                    *(uint32_t*)&Ps[row0 * PSH2 + col] = h2u(p0, p1);
                    *(uint32_t*)&Ps[row1 * PSH2 + col] = h2u(p2, p3);
                }
            }
        }
        __syncthreads();

        // PV: warp owns rows w*16 .. w*16+15, k = 128
        #pragma unroll
        for (int kk = 0; kk < 8; kk++) {
            const int kb = kk * 16;
            const int pr = (w * 16 + g) * PSH2 + kb + 2 * tg;
            uint32_t a[4];
            a[0] = *(const uint32_t*)&Ps[pr];
            a[1] = *(const uint32_t*)&Ps[pr + 8 * PSH2];
            a[2] = *(const uint32_t*)&Ps[pr + 8];
            a[3] = *(const uint32_t*)&Ps[pr + 8 * PSH2 + 8];
            #pragma unroll
            for (int j = 0; j < 8; j++) {
                const int nb = j * 8;
                uint32_t b0 = *(const uint32_t*)&VsT[(nb + g) * VSH2 + kb + 2 * tg];
                uint32_t b1 = *(const uint32_t*)&VsT[(nb + g) * VSH2 + kb + 2 * tg + 8];
                mma16(oacc[j], a, b0, b1);
            }
        }
    }

    // ctx write fp16, [B, S, H*Dh]
    #pragma unroll
    for (int j = 0; j < 8; j++) {
        const int col = hh * HEAD_DIM + j * 8 + 2 * tg;
        const int row0 = m0 + w * 16 + g;
        const int row1 = row0 + 8;
        *(__half2*)&g_ctxh[(size_t)(bb * SEQ + row0) * D_MODEL + col] =
            __floats2half2_rn(oacc[j][0], oacc[j][1]);
        *(__half2*)&g_ctxh[(size_t)(bb * SEQ + row1) * D_MODEL + col] =
            __floats2half2_rn(oacc[j][2], oacc[j][3]);
    }
}

// ---------------------------------------------------------------------------
extern "C" void kernel_launch(void* const* d_in, const int* in_sizes, int n_in,
                              void* d_out, int out_size)
{
    const float* q  = (const float*)d_in[0];
    const float* k  = (const float*)d_in[1];
    const float* v  = (const float*)d_in[2];
    const float* Wq = (const float*)d_in[3];
    const float* bq = (const float*)d_in[4];
    const float* Wk = (const float*)d_in[5];
    const float* bk = (const float*)d_in[6];
    const float* Wv = (const float*)d_in[7];
    const float* bv = (const float*)d_in[8];
    const float* Wo = (const float*)d_in[9];
    const float* bo = (const float*)d_in[10];
    float* out  = (float*)d_out;
    float* attn = out + OUT_ELEMS;

    cudaFuncSetAttribute(attn_fused,
                         cudaFuncAttributeMaxDynamicSharedMemorySize, ATT_SMEM);

    convert_all<<<dim3(2048, 7), 256>>>(q, k, v, Wq, Wk, Wv, Wo);

    gemm_qkv<<<dim3(24, M_ROWS / 128), 256, GEMM_SMEM>>>(bq, bk, bv);

    attn_fused<<<dim3(NTILES, NBH), 256, ATT_SMEM>>>(attn);

    gemm_out<<<dim3(D_MODEL / 128, M_ROWS / 128), 256, GEMM_SMEM>>>(bo, out);
}

// round 8
// speedup vs baseline: 8.4828x; 1.9221x over previous
#include <cuda_runtime.h>
#include <cuda_fp16.h>
#include <stdint.h>

// Problem constants
#define D_MODEL   1024
#define N_HEADS   16
#define HEAD_DIM  64
#define BATCH     2
#define SEQ       2048
#define M_ROWS    4096
#define OUT_ELEMS ((size_t)M_ROWS * D_MODEL)
#define SCALE_F   0.125f
#define NBH       32
#define NTILES    16

// fp16 scratch (device globals; no allocation allowed)
__device__ __half g_qh[M_ROWS * D_MODEL];
__device__ __half g_kh[M_ROWS * D_MODEL];
__device__ __half g_vh[M_ROWS * D_MODEL];
__device__ __half g_Wqh[D_MODEL * D_MODEL];
__device__ __half g_Wkh[D_MODEL * D_MODEL];
__device__ __half g_Wvh[D_MODEL * D_MODEL];
__device__ __half g_Woh[D_MODEL * D_MODEL];
__device__ __half g_Qh[NBH * SEQ * HEAD_DIM];   // pre-scaled by SCALE_F
__device__ __half g_Kh[NBH * SEQ * HEAD_DIM];
__device__ __half g_Vh[NBH * SEQ * HEAD_DIM];
__device__ __half g_ctxh[M_ROWS * D_MODEL];

// ---------------------------------------------------------------------------
// helpers
// ---------------------------------------------------------------------------
__device__ __forceinline__ uint32_t h2u(float a, float b) {
    __half2 h = __floats2half2_rn(a, b);
    return *reinterpret_cast<uint32_t*>(&h);
}

__device__ __forceinline__ void mma16(float* c, const uint32_t* a,
                                      uint32_t b0, uint32_t b1) {
    asm volatile(
        "mma.sync.aligned.m16n8k16.row.col.f32.f16.f16.f32 "
        "{%0,%1,%2,%3},{%4,%5,%6,%7},{%8,%9},{%0,%1,%2,%3};\n"
        : "+f"(c[0]), "+f"(c[1]), "+f"(c[2]), "+f"(c[3])
        : "r"(a[0]), "r"(a[1]), "r"(a[2]), "r"(a[3]), "r"(b0), "r"(b1));
}

__device__ __forceinline__ void ldsm4(uint32_t* r, uint32_t addr) {
    asm volatile("ldmatrix.sync.aligned.m8n8.x4.shared.b16 {%0,%1,%2,%3}, [%4];"
        : "=r"(r[0]), "=r"(r[1]), "=r"(r[2]), "=r"(r[3]) : "r"(addr));
}
__device__ __forceinline__ void ldsm4t(uint32_t* r, uint32_t addr) {
    asm volatile("ldmatrix.sync.aligned.m8n8.x4.trans.shared.b16 {%0,%1,%2,%3}, [%4];"
        : "=r"(r[0]), "=r"(r[1]), "=r"(r[2]), "=r"(r[3]) : "r"(addr));
}

__device__ __forceinline__ void cp16(uint32_t dst, const void* src) {
    asm volatile("cp.async.ca.shared.global [%0], [%1], 16;\n"
                 :: "r"(dst), "l"(src));
}
#define CP_COMMIT() asm volatile("cp.async.commit_group;\n" ::)
#define CP_WAIT2()  asm volatile("cp.async.wait_group 2;\n" ::)
#define CP_WAIT0()  asm volatile("cp.async.wait_group 0;\n" ::)

// ldmatrix per-lane offset builders (byte offsets within a tile region)
// A 16x16 (rows=m, row-major, stride S halves)
__device__ __forceinline__ uint32_t a_off(int lane, int S) {
    return (uint32_t)((((lane & 7) + ((lane >> 3) & 1) * 8) * S) * 2 + (lane >> 4) * 16);
}
// B pair 16(n) x 16(k) from [n][k] rows; regs {b0n0,b1n0,b0n1,b1n1}
__device__ __forceinline__ uint32_t b_off(int lane, int S) {
    return (uint32_t)((((lane & 7) + (lane >> 4) * 8) * S) * 2 + ((lane >> 3) & 1) * 16);
}
// V trans pair: 16(k) x 16(d) from [k][d] rows; regs {b0d0,b1d0,b0d1,b1d1}
__device__ __forceinline__ uint32_t v_off(int lane, int S) {
    return (uint32_t)((((lane & 7) + ((lane >> 3) & 1) * 8) * S) * 2 + (lane >> 4) * 16);
}

// ---------------------------------------------------------------------------
// Convert fp32 -> fp16 (7 segments)
// ---------------------------------------------------------------------------
__global__ __launch_bounds__(256)
void convert_all(const float* __restrict__ q, const float* __restrict__ k,
                 const float* __restrict__ v, const float* __restrict__ Wq,
                 const float* __restrict__ Wk, const float* __restrict__ Wv,
                 const float* __restrict__ Wo)
{
    const int seg = blockIdx.y;
    const float* src; __half* dst; int n;
    switch (seg) {
        case 0: src = q;  dst = g_qh;  n = M_ROWS * D_MODEL; break;
        case 1: src = k;  dst = g_kh;  n = M_ROWS * D_MODEL; break;
        case 2: src = v;  dst = g_vh;  n = M_ROWS * D_MODEL; break;
        case 3: src = Wq; dst = g_Wqh; n = D_MODEL * D_MODEL; break;
        case 4: src = Wk; dst = g_Wkh; n = D_MODEL * D_MODEL; break;
        case 5: src = Wv; dst = g_Wvh; n = D_MODEL * D_MODEL; break;
        default: src = Wo; dst = g_Woh; n = D_MODEL * D_MODEL; break;
    }
    const int idx = (blockIdx.x * 256 + threadIdx.x) * 8;
    if (idx >= n) return;
    float4 a = *(const float4*)&src[idx];
    float4 b = *(const float4*)&src[idx + 4];
    uint4 o;
    o.x = h2u(a.x, a.y); o.y = h2u(a.z, a.w);
    o.z = h2u(b.x, b.y); o.w = h2u(b.z, b.w);
    *(uint4*)&dst[idx] = o;
}

// ---------------------------------------------------------------------------
// GEMM core: BM=BN=128, BK=16, cp.async 4-stage, ldmatrix fragments.
// ---------------------------------------------------------------------------
#define GKS 24
#define GSTAGE (128 * GKS)
#define GEMM_SMEM (4 * 2 * GSTAGE * 2)   // 49,152 B

#define GEMM_MAINLOOP(Xsrc, Wsrc)                                              \
    float acc[4][4][4] = {};                                                   \
    const uint32_t sbase = (uint32_t)__cvta_generic_to_shared(smh);            \
    const uint32_t xdst0 = sbase + (lr * GKS + lc) * 2;                        \
    const uint32_t wdst0 = xdst0 + GSTAGE * 2;                                 \
    const uint32_t aof = a_off(lane, GKS);                                     \
    const uint32_t bof = b_off(lane, GKS);                                     \
    _Pragma("unroll")                                                          \
    for (int s = 0; s < 3; s++) {                                              \
        cp16(xdst0 + s * 2 * GSTAGE * 2, (Xsrc) + s * 16);                     \
        cp16(wdst0 + s * 2 * GSTAGE * 2, (Wsrc) + s * 16);                     \
        CP_COMMIT();                                                           \
    }                                                                          \
    _Pragma("unroll 1")                                                        \
    for (int it = 0; it < 64; it++) {                                          \
        CP_WAIT2();                                                            \
        __syncthreads();                                                       \
        if (it + 3 < 64) {                                                     \
            const int s = (it + 3) & 3;                                        \
            cp16(xdst0 + s * 2 * GSTAGE * 2, (Xsrc) + (it + 3) * 16);          \
            cp16(wdst0 + s * 2 * GSTAGE * 2, (Wsrc) + (it + 3) * 16);          \
        }                                                                      \
        CP_COMMIT();                                                           \
        const uint32_t xs_u = sbase + ((it & 3) * 2 * GSTAGE) * 2;             \
        const uint32_t ws_u = xs_u + GSTAGE * 2;                               \
        uint32_t a[4][4], b[2][4];                                             \
        _Pragma("unroll")                                                      \
        for (int i = 0; i < 4; i++)                                            \
            ldsm4(a[i], xs_u + aof + (wr * 64 + i * 16) * GKS * 2);            \
        ldsm4(b[0], ws_u + bof + (wc * 32) * GKS * 2);                         \
        ldsm4(b[1], ws_u + bof + (wc * 32 + 16) * GKS * 2);                    \
        _Pragma("unroll")                                                      \
        for (int jp = 0; jp < 2; jp++)                                         \
            _Pragma("unroll")                                                  \
            for (int jj = 0; jj < 2; jj++)                                     \
                _Pragma("unroll")                                              \
                for (int i = 0; i < 4; i++)                                    \
                    mma16(acc[i][jp * 2 + jj], a[i], b[jp][jj * 2], b[jp][jj * 2 + 1]); \
    }

// QKV projection (one launch; sel = blockIdx.x>>3)
__global__ __launch_bounds__(256, 2)
void gemm_qkv(const float* __restrict__ bq, const float* __restrict__ bk,
              const float* __restrict__ bv)
{
    extern __shared__ __half smh[];
    const int sel = blockIdx.x >> 3;
    const int n0  = (blockIdx.x & 7) * 128;
    const int m0  = blockIdx.y * 128;

    const __half* X = sel == 0 ? g_qh : sel == 1 ? g_kh : g_vh;
    const __half* W = sel == 0 ? g_Wqh : sel == 1 ? g_Wkh : g_Wvh;
    const float* bias = sel == 0 ? bq : sel == 1 ? bk : bv;
    __half* outp = sel == 0 ? g_Qh : sel == 1 ? g_Kh : g_Vh;
    const float oscale = sel == 0 ? SCALE_F : 1.f;

    const int t = threadIdx.x, lane = t & 31, w = t >> 5;
    const int g = lane >> 2, tg = lane & 3;
    const int wr = w >> 2, wc = w & 3;
    const int lr = t >> 1, lc = (t & 1) * 8;

    const __half* Xsrc = X + (size_t)(m0 + lr) * D_MODEL + lc;
    const __half* Wsrc = W + (size_t)(n0 + lr) * D_MODEL + lc;

    GEMM_MAINLOOP(Xsrc, Wsrc)

    #pragma unroll
    for (int j = 0; j < 4; j++) {
        const int colw = n0 + wc * 32 + j * 8 + 2 * tg;
        const float bz0 = bias[colw];
        const float bz1 = bias[colw + 1];
        const int hh = colw >> 6;
        const int dd = colw & (HEAD_DIM - 1);
        #pragma unroll
        for (int i = 0; i < 4; i++) {
            const int row0 = m0 + wr * 64 + i * 16 + g;
            const int row1 = row0 + 8;
            {
                const int b = row0 >> 11, s = row0 & (SEQ - 1);
                *(__half2*)&outp[(((size_t)(b * N_HEADS + hh) * SEQ + s)) * HEAD_DIM + dd] =
                    __floats2half2_rn((acc[i][j][0] + bz0) * oscale,
                                      (acc[i][j][1] + bz1) * oscale);
            }
            {
                const int b = row1 >> 11, s = row1 & (SEQ - 1);
                *(__half2*)&outp[(((size_t)(b * N_HEADS + hh) * SEQ + s)) * HEAD_DIM + dd] =
                    __floats2half2_rn((acc[i][j][2] + bz0) * oscale,
                                      (acc[i][j][3] + bz1) * oscale);
            }
        }
    }
}

// Output projection
__global__ __launch_bounds__(256, 2)
void gemm_out(const float* __restrict__ bo, float* __restrict__ outp)
{
    extern __shared__ __half smh[];
    const int n0 = blockIdx.x * 128;
    const int m0 = blockIdx.y * 128;

    const int t = threadIdx.x, lane = t & 31, w = t >> 5;
    const int g = lane >> 2, tg = lane & 3;
    const int wr = w >> 2, wc = w & 3;
    const int lr = t >> 1, lc = (t & 1) * 8;

    const __half* Xsrc = g_ctxh + (size_t)(m0 + lr) * D_MODEL + lc;
    const __half* Wsrc = g_Woh + (size_t)(n0 + lr) * D_MODEL + lc;

    GEMM_MAINLOOP(Xsrc, Wsrc)

    #pragma unroll
    for (int j = 0; j < 4; j++) {
        const int col = n0 + wc * 32 + j * 8 + 2 * tg;
        const float bz0 = bo[col];
        const float bz1 = bo[col + 1];
        #pragma unroll
        for (int i = 0; i < 4; i++) {
            const int row0 = m0 + wr * 64 + i * 16 + g;
            const int row1 = row0 + 8;
            *(float2*)&outp[(size_t)row0 * D_MODEL + col] =
                make_float2(acc[i][j][0] + bz0, acc[i][j][1] + bz1);
            *(float2*)&outp[(size_t)row1 * D_MODEL + col] =
                make_float2(acc[i][j][2] + bz0, acc[i][j][3] + bz1);
        }
    }
}

// ---------------------------------------------------------------------------
// Fused attention (per bh, 128-row m-tile): phase A online stats with
// double-buffered K; phase B recompute S, write attn once, O += P V.
// ---------------------------------------------------------------------------
#define QKS  72
#define KBUF (128 * QKS)            // halves
#define VSK  72
#define PSH2 136
#define ATT_SMEM (1024 + 128*QKS*2 + 2*KBUF*2 + 128*VSK*2 + 128*PSH2*2)  // 109,568

__global__ __launch_bounds__(256, 2)
void attn_fused(float* __restrict__ attnOut)
{
    const int m0 = blockIdx.x * 128;
    const int bh = blockIdx.y;
    const int bb = bh >> 4, hh = bh & 15;

    extern __shared__ char smc[];
    float2* rs  = (float2*)smc;                       // [128] (M, 1/L)
    __half* Qs  = (__half*)(smc + 1024);              // [128][QKS]
    __half* Ks0 = Qs + 128 * QKS;                     // [2][128][QKS]
    __half* Vs  = Ks0 + 2 * KBUF;                     // [128][VSK]  (rows = k)
    __half* Ps  = Vs + 128 * VSK;                     // [128][PSH2]

    const __half* Qg = g_Qh + ((size_t)bh * SEQ + m0) * HEAD_DIM;
    const __half* Kg = g_Kh + (size_t)bh * SEQ * HEAD_DIM;
    const __half* Vg = g_Vh + (size_t)bh * SEQ * HEAD_DIM;
    float* attnP = attnOut + (size_t)bh * SEQ * SEQ + (size_t)m0 * SEQ;

    const int t = threadIdx.x, lane = t & 31, w = t >> 5;
    const int g = lane >> 2, tg = lane & 3;
    const int wr = w >> 2, wc = w & 3;

    const uint32_t qs_u  = (uint32_t)__cvta_generic_to_shared(Qs);
    const uint32_t ks_u0 = (uint32_t)__cvta_generic_to_shared(Ks0);
    const uint32_t vs_u  = (uint32_t)__cvta_generic_to_shared(Vs);
    const uint32_t ps_u  = (uint32_t)__cvta_generic_to_shared(Ps);

    const uint32_t aofQ = a_off(lane, QKS);
    const uint32_t bofK = b_off(lane, QKS);
    const uint32_t aofP = a_off(lane, PSH2);
    const uint32_t vofV = v_off(lane, VSK);

    // V staging coords: 2 threads per row, 32 halves (64 B) each
    const int vrow = t >> 1;
    const int vcol = (t & 1) * 32;

    // stage Q once
    #pragma unroll
    for (int rep = 0; rep < 4; rep++) {
        const int c = rep * 256 + t;
        const int r = c >> 3, o = (c & 7) * 8;
        cp16(qs_u + (r * QKS + o) * 2, Qg + (size_t)r * HEAD_DIM + o);
    }
    CP_COMMIT();
    // preload K(0)
    #pragma unroll
    for (int rep = 0; rep < 4; rep++) {
        const int c = rep * 256 + t;
        const int r = c >> 3, o = (c & 7) * 8;
        cp16(ks_u0 + (r * QKS + o) * 2, Kg + (size_t)r * HEAD_DIM + o);
    }
    CP_COMMIT();

    // ---- Phase A: online row stats ----
    float mrun[8], lrun[8];
    #pragma unroll
    for (int s = 0; s < 8; s++) { mrun[s] = -1e30f; lrun[s] = 0.f; }

    #pragma unroll 1
    for (int kt = 0; kt < NTILES; kt++) {
        CP_WAIT0();
        __syncthreads();
        if (kt + 1 < NTILES) {
            const uint32_t kd = ks_u0 + (((kt + 1) & 1) * KBUF) * 2;
            #pragma unroll
            for (int rep = 0; rep < 4; rep++) {
                const int c = rep * 256 + t;
                const int r = c >> 3, o = (c & 7) * 8;
                cp16(kd + (r * QKS + o) * 2,
                     Kg + (size_t)((kt + 1) * 128 + r) * HEAD_DIM + o);
            }
            CP_COMMIT();
        }
        const uint32_t ks_u = ks_u0 + ((kt & 1) * KBUF) * 2;

        #pragma unroll
        for (int h = 0; h < 2; h++) {
            float acc[4][2][4] = {};
            #pragma unroll
            for (int kk = 0; kk < 4; kk++) {
                const int kb = kk * 16;
                uint32_t a[4][4], b[4];
                #pragma unroll
                for (int i = 0; i < 4; i++)
                    ldsm4(a[i], qs_u + aofQ + ((wr * 64 + i * 16) * QKS + kb) * 2);
                ldsm4(b, ks_u + bofK + ((h * 64 + wc * 16) * QKS + kb) * 2);
                #pragma unroll
                for (int i = 0; i < 4; i++) {
                    mma16(acc[i][0], a[i], b[0], b[1]);
                    mma16(acc[i][1], a[i], b[2], b[3]);
                }
            }
            #pragma unroll
            for (int i = 0; i < 4; i++) {
                #pragma unroll
                for (int half = 0; half < 2; half++) {
                    const int s = i * 2 + half;
                    const float v0 = acc[i][0][half * 2];
                    const float v1 = acc[i][0][half * 2 + 1];
                    const float v2 = acc[i][1][half * 2];
                    const float v3 = acc[i][1][half * 2 + 1];
                    const float tm = fmaxf(fmaxf(v0, v1), fmaxf(v2, v3));
                    const float m2 = fmaxf(mrun[s], tm);
                    lrun[s] = lrun[s] * __expf(mrun[s] - m2)
                            + __expf(v0 - m2) + __expf(v1 - m2)
                            + __expf(v2 - m2) + __expf(v3 - m2);
                    mrun[s] = m2;
                }
            }
        }
    }

    // reduce (m,l): tg lanes, then wc via smem
    #pragma unroll
    for (int s = 0; s < 8; s++) {
        #pragma unroll
        for (int off = 1; off <= 2; off <<= 1) {
            const float mo = __shfl_xor_sync(0xFFFFFFFFu, mrun[s], off);
            const float lo = __shfl_xor_sync(0xFFFFFFFFu, lrun[s], off);
            const float m2 = fmaxf(mrun[s], mo);
            lrun[s] = lrun[s] * __expf(mrun[s] - m2) + lo * __expf(mo - m2);
            mrun[s] = m2;
        }
    }
    __syncthreads();
    {
        float* stm = (float*)Ps;
        float* stl = stm + 512;
        if (tg == 0) {
            #pragma unroll
            for (int s = 0; s < 8; s++) {
                const int i = s >> 1, half = s & 1;
                const int row = wr * 64 + i * 16 + half * 8 + g;
                stm[row * 4 + wc] = mrun[s];
                stl[row * 4 + wc] = lrun[s];
            }
        }
        __syncthreads();
        if (t < 128) {
            float M = stm[t * 4];
            #pragma unroll
            for (int c = 1; c < 4; c++) M = fmaxf(M, stm[t * 4 + c]);
            float L = 0.f;
            #pragma unroll
            for (int c = 0; c < 4; c++)
                L += stl[t * 4 + c] * __expf(stm[t * 4 + c] - M);
            rs[t] = make_float2(M, 1.f / L);
        }
        __syncthreads();
    }

    // ---- Phase B ----
    float oacc[8][4] = {};
    uint4 vreg[4];

    // prefetch V(0) into regs: 32 halves per thread (full row coverage)
    {
        const __half* vsrc = Vg + (size_t)vrow * HEAD_DIM + vcol;
        vreg[0] = *(const uint4*)(vsrc);
        vreg[1] = *(const uint4*)(vsrc + 8);
        vreg[2] = *(const uint4*)(vsrc + 16);
        vreg[3] = *(const uint4*)(vsrc + 24);
    }
    // preload K(0) for phase B
    #pragma unroll
    for (int rep = 0; rep < 4; rep++) {
        const int c = rep * 256 + t;
        const int r = c >> 3, o = (c & 7) * 8;
        cp16(ks_u0 + (r * QKS + o) * 2, Kg + (size_t)r * HEAD_DIM + o);
    }
    CP_COMMIT();

    #pragma unroll 1
    for (int kt = 0; kt < NTILES; kt++) {
        CP_WAIT0();
        __syncthreads();
        // store V(kt) regs -> Vs[k][d] (full 64-half rows)
        {
            __half* vd = &Vs[vrow * VSK + vcol];
            *(uint4*)(vd)      = vreg[0];
            *(uint4*)(vd + 8)  = vreg[1];
            *(uint4*)(vd + 16) = vreg[2];
            *(uint4*)(vd + 24) = vreg[3];
        }
        if (kt + 1 < NTILES) {
            const uint32_t kd = ks_u0 + (((kt + 1) & 1) * KBUF) * 2;
            #pragma unroll
            for (int rep = 0; rep < 4; rep++) {
                const int c = rep * 256 + t;
                const int r = c >> 3, o = (c & 7) * 8;
                cp16(kd + (r * QKS + o) * 2,
                     Kg + (size_t)((kt + 1) * 128 + r) * HEAD_DIM + o);
            }
            CP_COMMIT();
        }
        const uint32_t ks_u = ks_u0 + ((kt & 1) * KBUF) * 2;

        #pragma unroll
        for (int h = 0; h < 2; h++) {
            float acc[4][2][4] = {};
            #pragma unroll
            for (int kk = 0; kk < 4; kk++) {
                const int kb = kk * 16;
                uint32_t a[4][4], b[4];
                #pragma unroll
                for (int i = 0; i < 4; i++)
                    ldsm4(a[i], qs_u + aofQ + ((wr * 64 + i * 16) * QKS + kb) * 2);
                ldsm4(b, ks_u + bofK + ((h * 64 + wc * 16) * QKS + kb) * 2);
                #pragma unroll
                for (int i = 0; i < 4; i++) {
                    mma16(acc[i][0], a[i], b[0], b[1]);
                    mma16(acc[i][1], a[i], b[2], b[3]);
                }
            }
            // normalize, write attn (final fp32), stage fp16 P
            #pragma unroll
            for (int i = 0; i < 4; i++) {
                const int row0 = wr * 64 + i * 16 + g;
                const int row1 = row0 + 8;
                const float2 st0 = rs[row0];
                const float2 st1 = rs[row1];
                #pragma unroll
                for (int j = 0; j < 2; j++) {
                    const int col = h * 64 + wc * 16 + j * 8 + 2 * tg;
                    const float p0 = __expf(acc[i][j][0] - st0.x) * st0.y;
                    const float p1 = __expf(acc[i][j][1] - st0.x) * st0.y;
                    const float p2 = __expf(acc[i][j][2] - st1.x) * st1.y;
                    const float p3 = __expf(acc[i][j][3] - st1.x) * st1.y;
                    *(float2*)&attnP[(size_t)row0 * SEQ + kt * 128 + col] =
                        make_float2(p0, p1);
                    *(float2*)&attnP[(size_t)row1 * SEQ + kt * 128 + col] =
                        make_float2(p2, p3);
                    *(uint32_t*)&Ps[row0 * PSH2 + col] = h2u(p0, p1);
                    *(uint32_t*)&Ps[row1 * PSH2 + col] = h2u(p2, p3);
                }
            }
        }
        // prefetch V(kt+1) into regs (hidden under PV mma)
        if (kt + 1 < NTILES) {
            const __half* vsrc = Vg + (size_t)((kt + 1) * 128 + vrow) * HEAD_DIM + vcol;
            vreg[0] = *(const uint4*)(vsrc);
            vreg[1] = *(const uint4*)(vsrc + 8);
            vreg[2] = *(const uint4*)(vsrc + 16);
            vreg[3] = *(const uint4*)(vsrc + 24);
        }
        __syncthreads();   // Ps + Vs visible

        // PV: warp owns rows w*16..w*16+15
        #pragma unroll
        for (int kk = 0; kk < 8; kk++) {
            const int kb = kk * 16;
            uint32_t a[4];
            ldsm4(a, ps_u + aofP + (w * 16 * PSH2 + kb) * 2);
            #pragma unroll
            for (int jp = 0; jp < 4; jp++) {
                uint32_t b[4];
                ldsm4t(b, vs_u + vofV + (kb * VSK + jp * 16) * 2);
                mma16(oacc[jp * 2],     a, b[0], b[1]);
                mma16(oacc[jp * 2 + 1], a, b[2], b[3]);
            }
        }
    }

    // ctx write fp16, [B, S, H*Dh]
    #pragma unroll
    for (int j = 0; j < 8; j++) {
        const int col = hh * HEAD_DIM + j * 8 + 2 * tg;
        const int row0 = m0 + w * 16 + g;
        const int row1 = row0 + 8;
        *(__half2*)&g_ctxh[(size_t)(bb * SEQ + row0) * D_MODEL + col] =
            __floats2half2_rn(oacc[j][0], oacc[j][1]);
        *(__half2*)&g_ctxh[(size_t)(bb * SEQ + row1) * D_MODEL + col] =
            __floats2half2_rn(oacc[j][2], oacc[j][3]);
    }
}

// ---------------------------------------------------------------------------
extern "C" void kernel_launch(void* const* d_in, const int* in_sizes, int n_in,
                              void* d_out, int out_size)
{
    const float* q  = (const float*)d_in[0];
    const float* k  = (const float*)d_in[1];
    const float* v  = (const float*)d_in[2];
    const float* Wq = (const float*)d_in[3];
    const float* bq = (const float*)d_in[4];
    const float* Wk = (const float*)d_in[5];
    const float* bk = (const float*)d_in[6];
    const float* Wv = (const float*)d_in[7];
    const float* bv = (const float*)d_in[8];
    const float* Wo = (const float*)d_in[9];
    const float* bo = (const float*)d_in[10];
    float* out  = (float*)d_out;
    float* attn = out + OUT_ELEMS;

    cudaFuncSetAttribute(attn_fused,
                         cudaFuncAttributeMaxDynamicSharedMemorySize, ATT_SMEM);

    convert_all<<<dim3(2048, 7), 256>>>(q, k, v, Wq, Wk, Wv, Wo);

    gemm_qkv<<<dim3(24, M_ROWS / 128), 256, GEMM_SMEM>>>(bq, bk, bv);

    attn_fused<<<dim3(NTILES, NBH), 256, ATT_SMEM>>>(attn);

    gemm_out<<<dim3(D_MODEL / 128, M_ROWS / 128), 256, GEMM_SMEM>>>(bo, out);
}